// round 7
// baseline (speedup 1.0000x reference)
#include <cuda_runtime.h>
#include <cstdint>

// Problem dims (fixed by the dataset)
#define BB   64
#define CC   512
#define NN   1024
#define CQ   64
#define RTOT 640   // Wq(64) + Wk(64) + Wv(512) rows

// Scratch
__device__ float d_Y[(size_t)BB * RTOT * NN];        // f/g rows 0..127, h' rows 128..639
__device__ float d_scores[(size_t)BB * NN * NN];     // E = exp(leaky(scores)), tf32-rounded
__device__ float d_xr[(size_t)BB * CC * NN];         // x rounded to tf32 (rna)
__device__ float d_Wvr[(size_t)CC * CC];             // Wv rounded to tf32 (rna)
__device__ float d_partZ[(size_t)BB * 8 * NN];
__device__ float d_partSm[(size_t)BB * 8 * NN];
__device__ float d_colZ[(size_t)BB * NN];
__device__ float d_colSm[(size_t)BB * NN];

// ---------------------------------------------------------------------------
// helpers
// ---------------------------------------------------------------------------
__device__ __forceinline__ uint32_t f2tf(float f) {
    uint32_t u;
    asm("cvt.rna.tf32.f32 %0, %1;" : "=r"(u) : "f"(f));
    return u;
}

__device__ __forceinline__ void mma8(float4& d, const uint32_t a[4], const uint32_t b[2]) {
    asm volatile(
        "mma.sync.aligned.m16n8k8.row.col.f32.tf32.tf32.f32 "
        "{%0,%1,%2,%3}, {%4,%5,%6,%7}, {%8,%9}, {%0,%1,%2,%3};"
        : "+f"(d.x), "+f"(d.y), "+f"(d.z), "+f"(d.w)
        : "r"(a[0]), "r"(a[1]), "r"(a[2]), "r"(a[3]), "r"(b[0]), "r"(b[1]));
}

__device__ __forceinline__ void cp16(void* dst_smem, const void* src_gmem) {
    uint32_t d = (uint32_t)__cvta_generic_to_shared(dst_smem);
    asm volatile("cp.async.cg.shared.global [%0], [%1], 16;" :: "r"(d), "l"(src_gmem));
}
#define CP_COMMIT() asm volatile("cp.async.commit_group;")
#define CP_WAIT0()  asm volatile("cp.async.wait_group 0;")

// ---------------------------------------------------------------------------
// 64x64-warp-tile raw compute (operands already tf32 bits), one 128x128x16 chunk.
// 4 warps (2x2). A m-major [128][20] (20*gid+tig conflict-free),
// B k-major [16][136] (8*tig+gid conflict-free).
// ---------------------------------------------------------------------------
__device__ __forceinline__ void compute_raw64(
    const float (*As)[20], const float (*Bs)[136],
    float4 (&c)[4][8], int gid, int tig, int wm, int wn)
{
#pragma unroll
    for (int ks = 0; ks < 16; ks += 8) {
        uint32_t a[4][4], bfr[8][2];
#pragma unroll
        for (int f = 0; f < 4; f++) {
            const int r = wm + f * 16 + gid;
            a[f][0] = __float_as_uint(As[r][ks + tig]);
            a[f][1] = __float_as_uint(As[r + 8][ks + tig]);
            a[f][2] = __float_as_uint(As[r][ks + tig + 4]);
            a[f][3] = __float_as_uint(As[r + 8][ks + tig + 4]);
        }
#pragma unroll
        for (int g = 0; g < 8; g++) {
            const int n0 = wn + g * 8 + gid;
            bfr[g][0] = __float_as_uint(Bs[ks + tig][n0]);
            bfr[g][1] = __float_as_uint(Bs[ks + tig + 4][n0]);
        }
#pragma unroll
        for (int f = 0; f < 4; f++)
#pragma unroll
            for (int g = 0; g < 8; g++)
                mma8(c[f][g], a[f], bfr[g]);
    }
}

// ---------------------------------------------------------------------------
// 64x32-warp-tile split (3xTF32) variants for the precision-critical path.
// ---------------------------------------------------------------------------
__device__ __forceinline__ void compute_split_mA(
    const float (*As)[20], const float (*Bs)[136],
    float4 (&c)[4][4], int gid, int tig, int mw, int nw)
{
#pragma unroll
    for (int ks = 0; ks < 16; ks += 8) {
        uint32_t ahi[4][4], alo[4][4];
        uint32_t bhi[4][2], blo[4][2];
#pragma unroll
        for (int f = 0; f < 4; f++) {
            const int r = mw + f * 16 + gid;
            float a0 = As[r][ks + tig];
            float a1 = As[r + 8][ks + tig];
            float a2 = As[r][ks + tig + 4];
            float a3 = As[r + 8][ks + tig + 4];
            ahi[f][0] = f2tf(a0); ahi[f][1] = f2tf(a1);
            ahi[f][2] = f2tf(a2); ahi[f][3] = f2tf(a3);
            alo[f][0] = f2tf(a0 - __uint_as_float(ahi[f][0]));
            alo[f][1] = f2tf(a1 - __uint_as_float(ahi[f][1]));
            alo[f][2] = f2tf(a2 - __uint_as_float(ahi[f][2]));
            alo[f][3] = f2tf(a3 - __uint_as_float(ahi[f][3]));
        }
#pragma unroll
        for (int g = 0; g < 4; g++) {
            const int n0 = nw + g * 8 + gid;
            float b0 = Bs[ks + tig][n0];
            float b1 = Bs[ks + tig + 4][n0];
            bhi[g][0] = f2tf(b0); bhi[g][1] = f2tf(b1);
            blo[g][0] = f2tf(b0 - __uint_as_float(bhi[g][0]));
            blo[g][1] = f2tf(b1 - __uint_as_float(bhi[g][1]));
        }
#pragma unroll
        for (int f = 0; f < 4; f++)
#pragma unroll
            for (int g = 0; g < 4; g++) {
                mma8(c[f][g], ahi[f], blo[g]);
                mma8(c[f][g], alo[f], bhi[g]);
                mma8(c[f][g], ahi[f], bhi[g]);
            }
    }
}

__device__ __forceinline__ void compute_split_kA(
    const float (*As)[136], const float (*Bs)[136],
    float4 (&c)[4][4], int gid, int tig, int mw, int nw)
{
#pragma unroll
    for (int ks = 0; ks < 16; ks += 8) {
        uint32_t ahi[4][4], alo[4][4];
        uint32_t bhi[4][2], blo[4][2];
#pragma unroll
        for (int f = 0; f < 4; f++) {
            const int r = mw + f * 16 + gid;
            float a0 = As[ks + tig][r];
            float a1 = As[ks + tig][r + 8];
            float a2 = As[ks + tig + 4][r];
            float a3 = As[ks + tig + 4][r + 8];
            ahi[f][0] = f2tf(a0); ahi[f][1] = f2tf(a1);
            ahi[f][2] = f2tf(a2); ahi[f][3] = f2tf(a3);
            alo[f][0] = f2tf(a0 - __uint_as_float(ahi[f][0]));
            alo[f][1] = f2tf(a1 - __uint_as_float(ahi[f][1]));
            alo[f][2] = f2tf(a2 - __uint_as_float(ahi[f][2]));
            alo[f][3] = f2tf(a3 - __uint_as_float(ahi[f][3]));
        }
#pragma unroll
        for (int g = 0; g < 4; g++) {
            const int n0 = nw + g * 8 + gid;
            float b0 = Bs[ks + tig][n0];
            float b1 = Bs[ks + tig + 4][n0];
            bhi[g][0] = f2tf(b0); bhi[g][1] = f2tf(b1);
            blo[g][0] = f2tf(b0 - __uint_as_float(bhi[g][0]));
            blo[g][1] = f2tf(b1 - __uint_as_float(bhi[g][1]));
        }
#pragma unroll
        for (int f = 0; f < 4; f++)
#pragma unroll
            for (int g = 0; g < 4; g++) {
                mma8(c[f][g], ahi[f], blo[g]);
                mma8(c[f][g], alo[f], bhi[g]);
                mma8(c[f][g], ahi[f], bhi[g]);
            }
    }
}

// ---------------------------------------------------------------------------
// K0: round x and Wv to tf32 (rna) once.
// ---------------------------------------------------------------------------
__global__ __launch_bounds__(256) void round_x_kernel(const float* __restrict__ x)
{
    const size_t i = ((size_t)blockIdx.x * 256 + threadIdx.x) * 4;
    float4 v = *(const float4*)(x + i);
    v.x = __uint_as_float(f2tf(v.x));
    v.y = __uint_as_float(f2tf(v.y));
    v.z = __uint_as_float(f2tf(v.z));
    v.w = __uint_as_float(f2tf(v.w));
    *(float4*)(d_xr + i) = v;
}

__global__ __launch_bounds__(256) void round_wv_kernel(const float* __restrict__ Wv)
{
    const size_t i = ((size_t)blockIdx.x * 256 + threadIdx.x) * 4;
    float4 v = *(const float4*)(Wv + i);
    v.x = __uint_as_float(f2tf(v.x));
    v.y = __uint_as_float(f2tf(v.y));
    v.z = __uint_as_float(f2tf(v.z));
    v.w = __uint_as_float(f2tf(v.w));
    *(float4*)(d_Wvr + i) = v;
}

// ---------------------------------------------------------------------------
// K1a: f,g projection (rows 0..127 of Y) = [Wq;Wk] @ x.  SPLIT tf32, cp.async.
// 256 threads, 64x32 warp tiles.
// ---------------------------------------------------------------------------
__global__ __launch_bounds__(256) void qkv_fg_gemm(
    const float* __restrict__ x,
    const float* __restrict__ Wq,
    const float* __restrict__ Wk)
{
    __shared__ float As[2][128][20];
    __shared__ float Bs[2][16][136];

    const int b = blockIdx.z;
    const int col0 = blockIdx.x * 128;
    const float* xb = x + (size_t)b * CC * NN;

    const int tid = threadIdx.x, lane = tid & 31, warp = tid >> 5;
    const int gid = lane >> 2, tig = lane & 3;
    const int mw = (warp >> 2) * 64, nw = (warp & 3) * 32;

    const int am0 = tid >> 2;
    const int ak  = (tid & 3) * 4;
    const float* arow0 = Wq + (size_t)am0 * CC;
    const float* arow1 = Wk + (size_t)am0 * CC;
    const int bk0 = tid >> 5;
    const int bn  = (tid & 31) * 4;

    float4 c[4][4];
#pragma unroll
    for (int f = 0; f < 4; f++)
#pragma unroll
        for (int g = 0; g < 4; g++) c[f][g] = make_float4(0, 0, 0, 0);

    cp16(&As[0][am0][ak],       arow0 + ak);
    cp16(&As[0][am0 + 64][ak],  arow1 + ak);
    cp16(&Bs[0][bk0][bn],       xb + (size_t)bk0 * NN + col0 + bn);
    cp16(&Bs[0][bk0 + 8][bn],   xb + (size_t)(bk0 + 8) * NN + col0 + bn);
    CP_COMMIT();
    CP_WAIT0();
    __syncthreads();

    const int NS = CC / 16;   // 32
    for (int s = 0; s < NS; s++) {
        const int buf = s & 1;
        if (s + 1 < NS) {
            const int kc = (s + 1) * 16;
            const int nb = buf ^ 1;
            cp16(&As[nb][am0][ak],      arow0 + kc + ak);
            cp16(&As[nb][am0 + 64][ak], arow1 + kc + ak);
            cp16(&Bs[nb][bk0][bn],      xb + (size_t)(kc + bk0) * NN + col0 + bn);
            cp16(&Bs[nb][bk0 + 8][bn],  xb + (size_t)(kc + bk0 + 8) * NN + col0 + bn);
            CP_COMMIT();
        }
        compute_split_mA(As[buf], Bs[buf], c, gid, tig, mw, nw);
        CP_WAIT0();
        __syncthreads();
    }

    float* yb = d_Y + (size_t)b * RTOT * NN;
#pragma unroll
    for (int f = 0; f < 4; f++) {
        const int r = mw + f * 16 + gid;
#pragma unroll
        for (int g = 0; g < 4; g++) {
            const int col = col0 + nw + g * 8 + 2 * tig;
            *(float2*)(yb + (size_t)r * NN + col)       = make_float2(c[f][g].x, c[f][g].y);
            *(float2*)(yb + (size_t)(r + 8) * NN + col) = make_float2(c[f][g].z, c[f][g].w);
        }
    }
}

// ---------------------------------------------------------------------------
// K1b: h' = (Wvr @ xr) * mask[col], tf32-rounded on store.
// 128 threads, 4 warps 2x2, 64x64 warp tiles. Raw MMA, cp.async.
// ---------------------------------------------------------------------------
__global__ __launch_bounds__(128) void qkv_h_gemm(const float* __restrict__ mask)
{
    __shared__ float As[2][128][20];
    __shared__ float Bs[2][16][136];

    const int b = blockIdx.z;
    const int row0 = blockIdx.y * 128;
    const int col0 = blockIdx.x * 128;
    const float* xb = d_xr + (size_t)b * CC * NN;

    const int tid = threadIdx.x, lane = tid & 31, warp = tid >> 5;
    const int gid = lane >> 2, tig = lane & 3;
    const int wm = (warp >> 1) * 64, wn = (warp & 1) * 64;

    // A: each thread loads full k=16 of one row (4 cp16)
    const float* arow = d_Wvr + (size_t)(row0 + tid) * CC;
    // B: bk = tid>>5 (0..3), rows bk, bk+4, bk+8, bk+12
    const int bk = tid >> 5;
    const int bn = (tid & 31) * 4;

    float4 c[4][8];
#pragma unroll
    for (int f = 0; f < 4; f++)
#pragma unroll
        for (int g = 0; g < 8; g++) c[f][g] = make_float4(0, 0, 0, 0);

#pragma unroll
    for (int q = 0; q < 4; q++) {
        cp16(&As[0][tid][q * 4], arow + q * 4);
        cp16(&Bs[0][bk + q * 4][bn], xb + (size_t)(bk + q * 4) * NN + col0 + bn);
    }
    CP_COMMIT();
    CP_WAIT0();
    __syncthreads();

    const int NS = CC / 16;  // 32
    for (int s = 0; s < NS; s++) {
        const int buf = s & 1;
        if (s + 1 < NS) {
            const int kc = (s + 1) * 16;
            const int nb = buf ^ 1;
#pragma unroll
            for (int q = 0; q < 4; q++) {
                cp16(&As[nb][tid][q * 4], arow + kc + q * 4);
                cp16(&Bs[nb][bk + q * 4][bn], xb + (size_t)(kc + bk + q * 4) * NN + col0 + bn);
            }
            CP_COMMIT();
        }
        compute_raw64(As[buf], Bs[buf], c, gid, tig, wm, wn);
        CP_WAIT0();
        __syncthreads();
    }

    float* yb = d_Y + (size_t)b * RTOT * NN + (size_t)(2 * CQ + row0) * NN;
    const float* mb = mask + (size_t)b * NN;
#pragma unroll
    for (int f = 0; f < 4; f++) {
        const int r = wm + f * 16 + gid;
#pragma unroll
        for (int g = 0; g < 8; g++) {
            const int col = col0 + wn + g * 8 + 2 * tig;
            float2 mv = *(const float2*)(mb + col);
            float2 o0, o1;
            o0.x = __uint_as_float(f2tf(c[f][g].x * mv.x));
            o0.y = __uint_as_float(f2tf(c[f][g].y * mv.y));
            o1.x = __uint_as_float(f2tf(c[f][g].z * mv.x));
            o1.y = __uint_as_float(f2tf(c[f][g].w * mv.y));
            *(float2*)(yb + (size_t)r * NN + col)       = o0;
            *(float2*)(yb + (size_t)(r + 8) * NN + col) = o1;
        }
    }
}

// ---------------------------------------------------------------------------
// K2: E[i][j] = tf32_round(exp(leaky(F^T G))), K=64, SPLIT tf32, cp.async.
// 256 threads, 64x32 warp tiles. Emits per-i-tile column partial sums.
// ---------------------------------------------------------------------------
__global__ __launch_bounds__(256) void scores_gemm_t(const float* __restrict__ mask)
{
    __shared__ float As[2][16][136];
    __shared__ float Bs[2][16][136];
    __shared__ float sZ[128];
    __shared__ float sSm[128];

    const int b  = blockIdx.z;
    const int it = blockIdx.y;
    const int i0 = it * 128;
    const int j0 = blockIdx.x * 128;
    const float* F = d_Y + (size_t)b * RTOT * NN;
    const float* G = F + (size_t)CQ * NN;

    const int tid = threadIdx.x, lane = tid & 31, warp = tid >> 5;
    const int gid = lane >> 2, tig = lane & 3;
    const int mw = (warp >> 2) * 64, nw = (warp & 3) * 32;
    const int bk0 = tid >> 5;
    const int bn  = (tid & 31) * 4;

    if (tid < 128) { sZ[tid] = 0.0f; sSm[tid] = 0.0f; }

    float4 c[4][4];
#pragma unroll
    for (int f = 0; f < 4; f++)
#pragma unroll
        for (int g = 0; g < 4; g++) c[f][g] = make_float4(0, 0, 0, 0);

    cp16(&As[0][bk0][bn],     F + (size_t)bk0 * NN + i0 + bn);
    cp16(&As[0][bk0 + 8][bn], F + (size_t)(bk0 + 8) * NN + i0 + bn);
    cp16(&Bs[0][bk0][bn],     G + (size_t)bk0 * NN + j0 + bn);
    cp16(&Bs[0][bk0 + 8][bn], G + (size_t)(bk0 + 8) * NN + j0 + bn);
    CP_COMMIT();
    CP_WAIT0();
    __syncthreads();

    const int NS = CQ / 16;  // 4
    for (int s = 0; s < NS; s++) {
        const int buf = s & 1;
        if (s + 1 < NS) {
            const int kc = (s + 1) * 16;
            const int nb = buf ^ 1;
            cp16(&As[nb][bk0][bn],     F + (size_t)(kc + bk0) * NN + i0 + bn);
            cp16(&As[nb][bk0 + 8][bn], F + (size_t)(kc + bk0 + 8) * NN + i0 + bn);
            cp16(&Bs[nb][bk0][bn],     G + (size_t)(kc + bk0) * NN + j0 + bn);
            cp16(&Bs[nb][bk0 + 8][bn], G + (size_t)(kc + bk0 + 8) * NN + j0 + bn);
            CP_COMMIT();
        }
        compute_split_kA(As[buf], Bs[buf], c, gid, tig, mw, nw);
        CP_WAIT0();
        __syncthreads();
    }

    float* S = d_scores + (size_t)b * NN * NN;
    const float* mb = mask + (size_t)b * NN;

    float mrow[4][2];
#pragma unroll
    for (int f = 0; f < 4; f++) {
        const int r = i0 + mw + f * 16 + gid;
        mrow[f][0] = __ldg(&mb[r]);
        mrow[f][1] = __ldg(&mb[r + 8]);
    }

#pragma unroll
    for (int g = 0; g < 4; g++) {
        const int colL = nw + g * 8 + 2 * tig;
        float z0 = 0, z1 = 0, sm0 = 0, sm1 = 0;
#pragma unroll
        for (int f = 0; f < 4; f++) {
            const int r = i0 + mw + f * 16 + gid;
            float s0 = c[f][g].x, s1 = c[f][g].y, s2 = c[f][g].z, s3 = c[f][g].w;
            s0 = s0 >= 0.0f ? s0 : 0.2f * s0;
            s1 = s1 >= 0.0f ? s1 : 0.2f * s1;
            s2 = s2 >= 0.0f ? s2 : 0.2f * s2;
            s3 = s3 >= 0.0f ? s3 : 0.2f * s3;
            float e0 = __expf(fminf(s0, 75.0f));
            float e1 = __expf(fminf(s1, 75.0f));
            float e2 = __expf(fminf(s2, 75.0f));
            float e3 = __expf(fminf(s3, 75.0f));
            *(float2*)(S + (size_t)r * NN + j0 + colL) =
                make_float2(__uint_as_float(f2tf(e0)), __uint_as_float(f2tf(e1)));
            *(float2*)(S + (size_t)(r + 8) * NN + j0 + colL) =
                make_float2(__uint_as_float(f2tf(e2)), __uint_as_float(f2tf(e3)));
            z0 += e0 + e2;   z1 += e1 + e3;
            sm0 += mrow[f][0] * e0 + mrow[f][1] * e2;
            sm1 += mrow[f][0] * e1 + mrow[f][1] * e3;
        }
        atomicAdd(&sZ[colL], z0);       atomicAdd(&sZ[colL + 1], z1);
        atomicAdd(&sSm[colL], sm0);     atomicAdd(&sSm[colL + 1], sm1);
    }
    __syncthreads();
    if (tid < 128) {
        const size_t off = ((size_t)b * 8 + it) * NN + j0 + tid;
        d_partZ[off]  = sZ[tid];
        d_partSm[off] = sSm[tid];
    }
}

// ---------------------------------------------------------------------------
// K2b: fold 8 i-tile partials into column sums.
// ---------------------------------------------------------------------------
__global__ __launch_bounds__(256) void reduce_sums()
{
    const int b = blockIdx.y;
    const int j = blockIdx.x * 256 + threadIdx.x;
    float z = 0.0f, s = 0.0f;
#pragma unroll
    for (int t = 0; t < 8; t++) {
        const size_t off = ((size_t)b * 8 + t) * NN + j;
        z += d_partZ[off];
        s += d_partSm[off];
    }
    d_colZ[(size_t)b * NN + j]  = z;
    d_colSm[(size_t)b * NN + j] = s;
}

// ---------------------------------------------------------------------------
// K4: out[c][m] = gamma*(sum_n h'[c][n]*E[n][m])*mask[m]/(Sm+eps*Z) + x[c][m]
// 128 threads, 4 warps 2x2, 64x64 warp tiles. Raw MMA, cp.async.
// ---------------------------------------------------------------------------
__global__ __launch_bounds__(128) void out_gemm_t(
    const float* __restrict__ x,
    const float* __restrict__ mask,
    const float* __restrict__ gamma,
    float* __restrict__ out)
{
    __shared__ float As[2][128][20];
    __shared__ float Bs[2][16][136];

    const int b  = blockIdx.z;
    const int c0 = blockIdx.y * 128;
    const int m0 = blockIdx.x * 128;
    const float* h  = d_Y + (size_t)b * RTOT * NN + (size_t)(2 * CQ) * NN;
    const float* Bt = d_scores + (size_t)b * NN * NN;

    const int tid = threadIdx.x, lane = tid & 31, warp = tid >> 5;
    const int gid = lane >> 2, tig = lane & 3;
    const int wm = (warp >> 1) * 64, wn = (warp & 1) * 64;

    const float* arow = h + (size_t)(c0 + tid) * NN;
    const int bk = tid >> 5;
    const int bn = (tid & 31) * 4;

    float4 c[4][8];
#pragma unroll
    for (int f = 0; f < 4; f++)
#pragma unroll
        for (int g = 0; g < 8; g++) c[f][g] = make_float4(0, 0, 0, 0);

#pragma unroll
    for (int q = 0; q < 4; q++) {
        cp16(&As[0][tid][q * 4], arow + q * 4);
        cp16(&Bs[0][bk + q * 4][bn], Bt + (size_t)(bk + q * 4) * NN + m0 + bn);
    }
    CP_COMMIT();
    CP_WAIT0();
    __syncthreads();

    const int NS = NN / 16;  // 64
    for (int s = 0; s < NS; s++) {
        const int buf = s & 1;
        if (s + 1 < NS) {
            const int kc = (s + 1) * 16;
            const int nb = buf ^ 1;
#pragma unroll
            for (int q = 0; q < 4; q++) {
                cp16(&As[nb][tid][q * 4], arow + kc + q * 4);
                cp16(&Bs[nb][bk + q * 4][bn], Bt + (size_t)(kc + bk + q * 4) * NN + m0 + bn);
            }
            CP_COMMIT();
        }
        compute_raw64(As[buf], Bs[buf], c, gid, tig, wm, wn);
        CP_WAIT0();
        __syncthreads();
    }

    const float g0 = gamma[0];
    const float* xb = x + (size_t)b * CC * NN;
    float* ob = out + (size_t)b * CC * NN;
    const float* mb = mask + (size_t)b * NN;
    const float* zc = d_colZ + (size_t)b * NN;
    const float* sc = d_colSm + (size_t)b * NN;

#pragma unroll
    for (int g = 0; g < 8; g++) {
        const int col = m0 + wn + g * 8 + 2 * tig;
        float2 mv = *(const float2*)(mb + col);
        float2 zv = *(const float2*)(zc + col);
        float2 sv = *(const float2*)(sc + col);
        const float w0 = g0 * mv.x / (sv.x + 1e-6f * zv.x);
        const float w1 = g0 * mv.y / (sv.y + 1e-6f * zv.y);
#pragma unroll
        for (int f = 0; f < 4; f++) {
            const int r = c0 + wm + f * 16 + gid;
            float2 x0 = *(const float2*)(xb + (size_t)r * NN + col);
            float2 x1 = *(const float2*)(xb + (size_t)(r + 8) * NN + col);
            float2 o0, o1;
            o0.x = c[f][g].x * w0 + x0.x;
            o0.y = c[f][g].y * w1 + x0.y;
            o1.x = c[f][g].z * w0 + x1.x;
            o1.y = c[f][g].w * w1 + x1.y;
            *(float2*)(ob + (size_t)r * NN + col)       = o0;
            *(float2*)(ob + (size_t)(r + 8) * NN + col) = o1;
        }
    }
}

// ---------------------------------------------------------------------------
extern "C" void kernel_launch(void* const* d_in, const int* in_sizes, int n_in,
                              void* d_out, int out_size)
{
    const float* x     = (const float*)d_in[0];
    const float* mask  = (const float*)d_in[1];
    const float* Wq    = (const float*)d_in[2];
    const float* Wk    = (const float*)d_in[3];
    const float* Wv    = (const float*)d_in[4];
    const float* gamma = (const float*)d_in[5];
    float* out = (float*)d_out;

    round_x_kernel <<<(size_t)BB * CC * NN / (256 * 4), 256>>>(x);
    round_wv_kernel<<<(size_t)CC * CC / (256 * 4), 256>>>(Wv);
    qkv_fg_gemm<<<dim3(NN / 128, 1, BB), 256>>>(x, Wq, Wk);
    qkv_h_gemm<<<dim3(NN / 128, CC / 128, BB), 128>>>(mask);
    scores_gemm_t<<<dim3(NN / 128, NN / 128, BB), 256>>>(mask);
    reduce_sums<<<dim3(NN / 256, BB), 256>>>();
    out_gemm_t<<<dim3(NN / 128, CC / 128, BB), 128>>>(x, mask, gamma, out);
}

// round 10
// speedup vs baseline: 1.3888x; 1.3888x over previous
#include <cuda_runtime.h>
#include <cstdint>

// Problem dims (fixed by the dataset)
#define BB   64
#define CC   512
#define NN   1024
#define CQ   64
#define RTOT 640

// Scratch
__device__ float d_Y[(size_t)BB * RTOT * NN];        // f/g rows 0..127, h' rows 128..639
__device__ float d_scores[(size_t)BB * NN * NN];     // E = exp(leaky(scores)), tf32-rounded
__device__ float d_xr[(size_t)BB * CC * NN];         // x rounded to tf32 (rna)
__device__ float d_Wvr[(size_t)CC * CC];             // Wv rounded to tf32 (rna)
__device__ float d_partZ[(size_t)BB * 8 * NN];
__device__ float d_partSm[(size_t)BB * 8 * NN];
__device__ float d_colZ[(size_t)BB * NN];
__device__ float d_colSm[(size_t)BB * NN];

// ---------------------------------------------------------------------------
// helpers
// ---------------------------------------------------------------------------
__device__ __forceinline__ uint32_t f2tf(float f) {
    uint32_t u;
    asm("cvt.rna.tf32.f32 %0, %1;" : "=r"(u) : "f"(f));
    return u;
}

__device__ __forceinline__ void mma8(float4& d, const uint32_t a[4], const uint32_t b[2]) {
    asm volatile(
        "mma.sync.aligned.m16n8k8.row.col.f32.tf32.tf32.f32 "
        "{%0,%1,%2,%3}, {%4,%5,%6,%7}, {%8,%9}, {%0,%1,%2,%3};"
        : "+f"(d.x), "+f"(d.y), "+f"(d.z), "+f"(d.w)
        : "r"(a[0]), "r"(a[1]), "r"(a[2]), "r"(a[3]), "r"(b[0]), "r"(b[1]));
}

__device__ __forceinline__ void cp16(void* dst_smem, const void* src_gmem) {
    uint32_t d = (uint32_t)__cvta_generic_to_shared(dst_smem);
    asm volatile("cp.async.cg.shared.global [%0], [%1], 16;" :: "r"(d), "l"(src_gmem));
}
#define CP_COMMIT() asm volatile("cp.async.commit_group;")
#define CP_WAIT0()  asm volatile("cp.async.wait_group 0;")

// ---------------------------------------------------------------------------
// k=16 inner computes (round-6 proven) for the split kernels
// ---------------------------------------------------------------------------
__device__ __forceinline__ void compute_split_mA(
    const float (*As)[20], const float (*Bs)[136],
    float4 (&c)[4][4], int gid, int tig, int mw, int nw)
{
#pragma unroll
    for (int ks = 0; ks < 16; ks += 8) {
        uint32_t ahi[4][4], alo[4][4];
        uint32_t bhi[4][2], blo[4][2];
#pragma unroll
        for (int f = 0; f < 4; f++) {
            const int r = mw + f * 16 + gid;
            float a0 = As[r][ks + tig];
            float a1 = As[r + 8][ks + tig];
            float a2 = As[r][ks + tig + 4];
            float a3 = As[r + 8][ks + tig + 4];
            ahi[f][0] = f2tf(a0); ahi[f][1] = f2tf(a1);
            ahi[f][2] = f2tf(a2); ahi[f][3] = f2tf(a3);
            alo[f][0] = f2tf(a0 - __uint_as_float(ahi[f][0]));
            alo[f][1] = f2tf(a1 - __uint_as_float(ahi[f][1]));
            alo[f][2] = f2tf(a2 - __uint_as_float(ahi[f][2]));
            alo[f][3] = f2tf(a3 - __uint_as_float(ahi[f][3]));
        }
#pragma unroll
        for (int g = 0; g < 4; g++) {
            const int n0 = nw + g * 8 + gid;
            float b0 = Bs[ks + tig][n0];
            float b1 = Bs[ks + tig + 4][n0];
            bhi[g][0] = f2tf(b0); bhi[g][1] = f2tf(b1);
            blo[g][0] = f2tf(b0 - __uint_as_float(bhi[g][0]));
            blo[g][1] = f2tf(b1 - __uint_as_float(bhi[g][1]));
        }
#pragma unroll
        for (int f = 0; f < 4; f++)
#pragma unroll
            for (int g = 0; g < 4; g++) {
                mma8(c[f][g], ahi[f], blo[g]);
                mma8(c[f][g], alo[f], bhi[g]);
                mma8(c[f][g], ahi[f], bhi[g]);
            }
    }
}

__device__ __forceinline__ void compute_split_kA(
    const float (*As)[136], const float (*Bs)[136],
    float4 (&c)[4][4], int gid, int tig, int mw, int nw)
{
#pragma unroll
    for (int ks = 0; ks < 16; ks += 8) {
        uint32_t ahi[4][4], alo[4][4];
        uint32_t bhi[4][2], blo[4][2];
#pragma unroll
        for (int f = 0; f < 4; f++) {
            const int r = mw + f * 16 + gid;
            float a0 = As[ks + tig][r];
            float a1 = As[ks + tig][r + 8];
            float a2 = As[ks + tig + 4][r];
            float a3 = As[ks + tig + 4][r + 8];
            ahi[f][0] = f2tf(a0); ahi[f][1] = f2tf(a1);
            ahi[f][2] = f2tf(a2); ahi[f][3] = f2tf(a3);
            alo[f][0] = f2tf(a0 - __uint_as_float(ahi[f][0]));
            alo[f][1] = f2tf(a1 - __uint_as_float(ahi[f][1]));
            alo[f][2] = f2tf(a2 - __uint_as_float(ahi[f][2]));
            alo[f][3] = f2tf(a3 - __uint_as_float(ahi[f][3]));
        }
#pragma unroll
        for (int g = 0; g < 4; g++) {
            const int n0 = nw + g * 8 + gid;
            float b0 = Bs[ks + tig][n0];
            float b1 = Bs[ks + tig + 4][n0];
            bhi[g][0] = f2tf(b0); bhi[g][1] = f2tf(b1);
            blo[g][0] = f2tf(b0 - __uint_as_float(bhi[g][0]));
            blo[g][1] = f2tf(b1 - __uint_as_float(bhi[g][1]));
        }
#pragma unroll
        for (int f = 0; f < 4; f++)
#pragma unroll
            for (int g = 0; g < 4; g++) {
                mma8(c[f][g], ahi[f], blo[g]);
                mma8(c[f][g], alo[f], bhi[g]);
                mma8(c[f][g], ahi[f], bhi[g]);
            }
    }
}

// ---------------------------------------------------------------------------
// k=32 raw inner compute for the bulk GEMMs.
// A m-major [128][40]: lane addr 40*gid+tig == 8*gid+tig (mod 32) conflict-free.
// B k-major [32][136]: 8*tig+gid conflict-free.
// ---------------------------------------------------------------------------
__device__ __forceinline__ void compute_raw32(
    const float (*As)[40], const float (*Bs)[136],
    float4 (&c)[4][4], int gid, int tig, int mw, int nw)
{
#pragma unroll
    for (int ks = 0; ks < 32; ks += 8) {
        uint32_t a[4][4], bfr[4][2];
#pragma unroll
        for (int f = 0; f < 4; f++) {
            const int r = mw + f * 16 + gid;
            a[f][0] = __float_as_uint(As[r][ks + tig]);
            a[f][1] = __float_as_uint(As[r + 8][ks + tig]);
            a[f][2] = __float_as_uint(As[r][ks + tig + 4]);
            a[f][3] = __float_as_uint(As[r + 8][ks + tig + 4]);
        }
#pragma unroll
        for (int g = 0; g < 4; g++) {
            const int n0 = nw + g * 8 + gid;
            bfr[g][0] = __float_as_uint(Bs[ks + tig][n0]);
            bfr[g][1] = __float_as_uint(Bs[ks + tig + 4][n0]);
        }
#pragma unroll
        for (int f = 0; f < 4; f++)
#pragma unroll
            for (int g = 0; g < 4; g++)
                mma8(c[f][g], a[f], bfr[g]);
    }
}

// dynamic-smem geometry for the k32 kernels
#define AS32_ELE (128 * 40)          // floats per A stage
#define BS32_ELE (32 * 136)          // floats per B stage
#define DSMEM32  ((2 * AS32_ELE + 2 * BS32_ELE) * 4)   // 75776 bytes

// ---------------------------------------------------------------------------
// K0: round x and Wv to tf32 (rna) once.
// ---------------------------------------------------------------------------
__global__ __launch_bounds__(256) void round_x_kernel(const float* __restrict__ x)
{
    const size_t i = ((size_t)blockIdx.x * 256 + threadIdx.x) * 4;
    float4 v = *(const float4*)(x + i);
    v.x = __uint_as_float(f2tf(v.x));
    v.y = __uint_as_float(f2tf(v.y));
    v.z = __uint_as_float(f2tf(v.z));
    v.w = __uint_as_float(f2tf(v.w));
    *(float4*)(d_xr + i) = v;
}

__global__ __launch_bounds__(256) void round_wv_kernel(const float* __restrict__ Wv)
{
    const size_t i = ((size_t)blockIdx.x * 256 + threadIdx.x) * 4;
    float4 v = *(const float4*)(Wv + i);
    v.x = __uint_as_float(f2tf(v.x));
    v.y = __uint_as_float(f2tf(v.y));
    v.z = __uint_as_float(f2tf(v.z));
    v.w = __uint_as_float(f2tf(v.w));
    *(float4*)(d_Wvr + i) = v;
}

// ---------------------------------------------------------------------------
// K1a: f,g projection = [Wq;Wk] @ x.  SPLIT tf32, k16, cp.async. (round-6 proven)
// ---------------------------------------------------------------------------
__global__ __launch_bounds__(256) void qkv_fg_gemm(
    const float* __restrict__ x,
    const float* __restrict__ Wq,
    const float* __restrict__ Wk)
{
    __shared__ float As[2][128][20];
    __shared__ float Bs[2][16][136];

    const int b = blockIdx.z;
    const int col0 = blockIdx.x * 128;
    const float* xb = x + (size_t)b * CC * NN;

    const int tid = threadIdx.x, lane = tid & 31, warp = tid >> 5;
    const int gid = lane >> 2, tig = lane & 3;
    const int mw = (warp >> 2) * 64, nw = (warp & 3) * 32;

    const int am0 = tid >> 2;
    const int ak  = (tid & 3) * 4;
    const float* arow0 = Wq + (size_t)am0 * CC;
    const float* arow1 = Wk + (size_t)am0 * CC;
    const int bk0 = tid >> 5;
    const int bn  = (tid & 31) * 4;

    float4 c[4][4];
#pragma unroll
    for (int f = 0; f < 4; f++)
#pragma unroll
        for (int g = 0; g < 4; g++) c[f][g] = make_float4(0, 0, 0, 0);

    cp16(&As[0][am0][ak],       arow0 + ak);
    cp16(&As[0][am0 + 64][ak],  arow1 + ak);
    cp16(&Bs[0][bk0][bn],       xb + (size_t)bk0 * NN + col0 + bn);
    cp16(&Bs[0][bk0 + 8][bn],   xb + (size_t)(bk0 + 8) * NN + col0 + bn);
    CP_COMMIT();
    CP_WAIT0();
    __syncthreads();

    const int NS = CC / 16;
    for (int s = 0; s < NS; s++) {
        const int buf = s & 1;
        if (s + 1 < NS) {
            const int kc = (s + 1) * 16;
            const int nb = buf ^ 1;
            cp16(&As[nb][am0][ak],      arow0 + kc + ak);
            cp16(&As[nb][am0 + 64][ak], arow1 + kc + ak);
            cp16(&Bs[nb][bk0][bn],      xb + (size_t)(kc + bk0) * NN + col0 + bn);
            cp16(&Bs[nb][bk0 + 8][bn],  xb + (size_t)(kc + bk0 + 8) * NN + col0 + bn);
            CP_COMMIT();
        }
        compute_split_mA(As[buf], Bs[buf], c, gid, tig, mw, nw);
        CP_WAIT0();
        __syncthreads();
    }

    float* yb = d_Y + (size_t)b * RTOT * NN;
#pragma unroll
    for (int f = 0; f < 4; f++) {
        const int r = mw + f * 16 + gid;
#pragma unroll
        for (int g = 0; g < 4; g++) {
            const int col = col0 + nw + g * 8 + 2 * tig;
            *(float2*)(yb + (size_t)r * NN + col)       = make_float2(c[f][g].x, c[f][g].y);
            *(float2*)(yb + (size_t)(r + 8) * NN + col) = make_float2(c[f][g].z, c[f][g].w);
        }
    }
}

// ---------------------------------------------------------------------------
// K1b: h' = (Wvr @ xr) * mask[col], tf32-rounded on store.
// Raw MMA, k32 chunks, dynamic smem, cp.async.
// ---------------------------------------------------------------------------
__global__ __launch_bounds__(256) void qkv_h_gemm(const float* __restrict__ mask)
{
    extern __shared__ float smem32[];

    const int b = blockIdx.z;
    const int row0 = blockIdx.y * 128;
    const int col0 = blockIdx.x * 128;
    const float* xb = d_xr + (size_t)b * CC * NN;

    const int tid = threadIdx.x, lane = tid & 31, warp = tid >> 5;
    const int gid = lane >> 2, tig = lane & 3;
    const int mw = (warp >> 2) * 64, nw = (warp & 3) * 32;

    // copy mapping: A: am=tid>>1 (0..127), ak=(tid&1)*16, 4x cp16
    //               B: bk=tid>>3 (0..31), bn=(tid&7)*16, 4x cp16
    const int am = tid >> 1;
    const int ak = (tid & 1) * 16;
    const float* arow = d_Wvr + (size_t)(row0 + am) * CC;
    const int bk = tid >> 3;
    const int bn = (tid & 7) * 16;

    float4 c[4][4];
#pragma unroll
    for (int f = 0; f < 4; f++)
#pragma unroll
        for (int g = 0; g < 4; g++) c[f][g] = make_float4(0, 0, 0, 0);

    auto As = [&](int st) { return (float (*)[40])(smem32 + st * AS32_ELE); };
    auto Bs = [&](int st) { return (float (*)[136])(smem32 + 2 * AS32_ELE + st * BS32_ELE); };

    {
#pragma unroll
        for (int q = 0; q < 4; q++) {
            cp16(&As(0)[am][ak + q * 4], arow + ak + q * 4);
            cp16(&Bs(0)[bk][bn + q * 4], xb + (size_t)bk * NN + col0 + bn + q * 4);
        }
        CP_COMMIT();
        CP_WAIT0();
        __syncthreads();
    }

    const int NS = CC / 32;   // 16
    for (int s = 0; s < NS; s++) {
        const int buf = s & 1;
        if (s + 1 < NS) {
            const int kc = (s + 1) * 32;
            const int nb = buf ^ 1;
#pragma unroll
            for (int q = 0; q < 4; q++) {
                cp16(&As(nb)[am][ak + q * 4], arow + kc + ak + q * 4);
                cp16(&Bs(nb)[bk][bn + q * 4], xb + (size_t)(kc + bk) * NN + col0 + bn + q * 4);
            }
            CP_COMMIT();
        }
        compute_raw32(As(buf), Bs(buf), c, gid, tig, mw, nw);
        CP_WAIT0();
        __syncthreads();
    }

    float* yb = d_Y + (size_t)b * RTOT * NN + (size_t)(2 * CQ + row0) * NN;
    const float* mb = mask + (size_t)b * NN;
#pragma unroll
    for (int f = 0; f < 4; f++) {
        const int r = mw + f * 16 + gid;
#pragma unroll
        for (int g = 0; g < 4; g++) {
            const int col = col0 + nw + g * 8 + 2 * tig;
            float2 mv = *(const float2*)(mb + col);
            float2 o0, o1;
            o0.x = __uint_as_float(f2tf(c[f][g].x * mv.x));
            o0.y = __uint_as_float(f2tf(c[f][g].y * mv.y));
            o1.x = __uint_as_float(f2tf(c[f][g].z * mv.x));
            o1.y = __uint_as_float(f2tf(c[f][g].w * mv.y));
            *(float2*)(yb + (size_t)r * NN + col)       = o0;
            *(float2*)(yb + (size_t)(r + 8) * NN + col) = o1;
        }
    }
}

// ---------------------------------------------------------------------------
// K2: E = tf32_round(exp(leaky(F^T G))), K=64, SPLIT tf32, k16, cp.async.
// Emits per-i-tile column partial sums of Z and mask*E. (round-6 proven)
// ---------------------------------------------------------------------------
__global__ __launch_bounds__(256) void scores_gemm_t(const float* __restrict__ mask)
{
    __shared__ float As[2][16][136];
    __shared__ float Bs[2][16][136];
    __shared__ float sZ[128];
    __shared__ float sSm[128];

    const int b  = blockIdx.z;
    const int it = blockIdx.y;
    const int i0 = it * 128;
    const int j0 = blockIdx.x * 128;
    const float* F = d_Y + (size_t)b * RTOT * NN;
    const float* G = F + (size_t)CQ * NN;

    const int tid = threadIdx.x, lane = tid & 31, warp = tid >> 5;
    const int gid = lane >> 2, tig = lane & 3;
    const int mw = (warp >> 2) * 64, nw = (warp & 3) * 32;
    const int bk0 = tid >> 5;
    const int bn  = (tid & 31) * 4;

    if (tid < 128) { sZ[tid] = 0.0f; sSm[tid] = 0.0f; }

    float4 c[4][4];
#pragma unroll
    for (int f = 0; f < 4; f++)
#pragma unroll
        for (int g = 0; g < 4; g++) c[f][g] = make_float4(0, 0, 0, 0);

    cp16(&As[0][bk0][bn],     F + (size_t)bk0 * NN + i0 + bn);
    cp16(&As[0][bk0 + 8][bn], F + (size_t)(bk0 + 8) * NN + i0 + bn);
    cp16(&Bs[0][bk0][bn],     G + (size_t)bk0 * NN + j0 + bn);
    cp16(&Bs[0][bk0 + 8][bn], G + (size_t)(bk0 + 8) * NN + j0 + bn);
    CP_COMMIT();
    CP_WAIT0();
    __syncthreads();

    const int NS = CQ / 16;  // 4
    for (int s = 0; s < NS; s++) {
        const int buf = s & 1;
        if (s + 1 < NS) {
            const int kc = (s + 1) * 16;
            const int nb = buf ^ 1;
            cp16(&As[nb][bk0][bn],     F + (size_t)(kc + bk0) * NN + i0 + bn);
            cp16(&As[nb][bk0 + 8][bn], F + (size_t)(kc + bk0 + 8) * NN + i0 + bn);
            cp16(&Bs[nb][bk0][bn],     G + (size_t)(kc + bk0) * NN + j0 + bn);
            cp16(&Bs[nb][bk0 + 8][bn], G + (size_t)(kc + bk0 + 8) * NN + j0 + bn);
            CP_COMMIT();
        }
        compute_split_kA(As[buf], Bs[buf], c, gid, tig, mw, nw);
        CP_WAIT0();
        __syncthreads();
    }

    float* S = d_scores + (size_t)b * NN * NN;
    const float* mb = mask + (size_t)b * NN;

    float mrow[4][2];
#pragma unroll
    for (int f = 0; f < 4; f++) {
        const int r = i0 + mw + f * 16 + gid;
        mrow[f][0] = __ldg(&mb[r]);
        mrow[f][1] = __ldg(&mb[r + 8]);
    }

#pragma unroll
    for (int g = 0; g < 4; g++) {
        const int colL = nw + g * 8 + 2 * tig;
        float z0 = 0, z1 = 0, sm0 = 0, sm1 = 0;
#pragma unroll
        for (int f = 0; f < 4; f++) {
            const int r = i0 + mw + f * 16 + gid;
            float s0 = c[f][g].x, s1 = c[f][g].y, s2 = c[f][g].z, s3 = c[f][g].w;
            s0 = s0 >= 0.0f ? s0 : 0.2f * s0;
            s1 = s1 >= 0.0f ? s1 : 0.2f * s1;
            s2 = s2 >= 0.0f ? s2 : 0.2f * s2;
            s3 = s3 >= 0.0f ? s3 : 0.2f * s3;
            float e0 = __expf(fminf(s0, 75.0f));
            float e1 = __expf(fminf(s1, 75.0f));
            float e2 = __expf(fminf(s2, 75.0f));
            float e3 = __expf(fminf(s3, 75.0f));
            *(float2*)(S + (size_t)r * NN + j0 + colL) =
                make_float2(__uint_as_float(f2tf(e0)), __uint_as_float(f2tf(e1)));
            *(float2*)(S + (size_t)(r + 8) * NN + j0 + colL) =
                make_float2(__uint_as_float(f2tf(e2)), __uint_as_float(f2tf(e3)));
            z0 += e0 + e2;   z1 += e1 + e3;
            sm0 += mrow[f][0] * e0 + mrow[f][1] * e2;
            sm1 += mrow[f][0] * e1 + mrow[f][1] * e3;
        }
        atomicAdd(&sZ[colL], z0);       atomicAdd(&sZ[colL + 1], z1);
        atomicAdd(&sSm[colL], sm0);     atomicAdd(&sSm[colL + 1], sm1);
    }
    __syncthreads();
    if (tid < 128) {
        const size_t off = ((size_t)b * 8 + it) * NN + j0 + tid;
        d_partZ[off]  = sZ[tid];
        d_partSm[off] = sSm[tid];
    }
}

// ---------------------------------------------------------------------------
// K2b: fold 8 i-tile partials into column sums.
// ---------------------------------------------------------------------------
__global__ __launch_bounds__(256) void reduce_sums()
{
    const int b = blockIdx.y;
    const int j = blockIdx.x * 256 + threadIdx.x;
    float z = 0.0f, s = 0.0f;
#pragma unroll
    for (int t = 0; t < 8; t++) {
        const size_t off = ((size_t)b * 8 + t) * NN + j;
        z += d_partZ[off];
        s += d_partSm[off];
    }
    d_colZ[(size_t)b * NN + j]  = z;
    d_colSm[(size_t)b * NN + j] = s;
}

// ---------------------------------------------------------------------------
// K4: out[c][m] = gamma*(sum_n h'[c][n]*E[n][m])*mask[m]/(Sm+eps*Z) + x[c][m]
// Raw MMA, k32 chunks, dynamic smem, cp.async.
// ---------------------------------------------------------------------------
__global__ __launch_bounds__(256) void out_gemm_t(
    const float* __restrict__ x,
    const float* __restrict__ mask,
    const float* __restrict__ gamma,
    float* __restrict__ out)
{
    extern __shared__ float smem32[];

    const int b  = blockIdx.z;
    const int c0 = blockIdx.y * 128;
    const int m0 = blockIdx.x * 128;
    const float* h  = d_Y + (size_t)b * RTOT * NN + (size_t)(2 * CQ) * NN;
    const float* Bt = d_scores + (size_t)b * NN * NN;

    const int tid = threadIdx.x, lane = tid & 31, warp = tid >> 5;
    const int gid = lane >> 2, tig = lane & 3;
    const int mw = (warp >> 2) * 64, nw = (warp & 3) * 32;

    const int am = tid >> 1;
    const int ak = (tid & 1) * 16;
    const float* arow = h + (size_t)(c0 + am) * NN;
    const int bk = tid >> 3;
    const int bn = (tid & 7) * 16;

    float4 c[4][4];
#pragma unroll
    for (int f = 0; f < 4; f++)
#pragma unroll
        for (int g = 0; g < 4; g++) c[f][g] = make_float4(0, 0, 0, 0);

    auto As = [&](int st) { return (float (*)[40])(smem32 + st * AS32_ELE); };
    auto Bs = [&](int st) { return (float (*)[136])(smem32 + 2 * AS32_ELE + st * BS32_ELE); };

    {
#pragma unroll
        for (int q = 0; q < 4; q++) {
            cp16(&As(0)[am][ak + q * 4], arow + ak + q * 4);
            cp16(&Bs(0)[bk][bn + q * 4], Bt + (size_t)bk * NN + m0 + bn + q * 4);
        }
        CP_COMMIT();
        CP_WAIT0();
        __syncthreads();
    }

    const int NS = NN / 32;  // 32
    for (int s = 0; s < NS; s++) {
        const int buf = s & 1;
        if (s + 1 < NS) {
            const int kc = (s + 1) * 32;
            const int nb = buf ^ 1;
#pragma unroll
            for (int q = 0; q < 4; q++) {
                cp16(&As(nb)[am][ak + q * 4], arow + kc + ak + q * 4);
                cp16(&Bs(nb)[bk][bn + q * 4], Bt + (size_t)(kc + bk) * NN + m0 + bn + q * 4);
            }
            CP_COMMIT();
        }
        compute_raw32(As(buf), Bs(buf), c, gid, tig, mw, nw);
        CP_WAIT0();
        __syncthreads();
    }

    const float g0 = gamma[0];
    const float* xb = x + (size_t)b * CC * NN;
    float* ob = out + (size_t)b * CC * NN;
    const float* mb = mask + (size_t)b * NN;
    const float* zc = d_colZ + (size_t)b * NN;
    const float* sc = d_colSm + (size_t)b * NN;

#pragma unroll
    for (int g = 0; g < 4; g++) {
        const int col = m0 + nw + g * 8 + 2 * tig;
        float2 mv = *(const float2*)(mb + col);
        float2 zv = *(const float2*)(zc + col);
        float2 sv = *(const float2*)(sc + col);
        const float w0 = g0 * mv.x / (sv.x + 1e-6f * zv.x);
        const float w1 = g0 * mv.y / (sv.y + 1e-6f * zv.y);
#pragma unroll
        for (int f = 0; f < 4; f++) {
            const int r = c0 + mw + f * 16 + gid;
            float2 x0 = *(const float2*)(xb + (size_t)r * NN + col);
            float2 x1 = *(const float2*)(xb + (size_t)(r + 8) * NN + col);
            float2 o0, o1;
            o0.x = c[f][g].x * w0 + x0.x;
            o0.y = c[f][g].y * w1 + x0.y;
            o1.x = c[f][g].z * w0 + x1.x;
            o1.y = c[f][g].w * w1 + x1.y;
            *(float2*)(ob + (size_t)r * NN + col)       = o0;
            *(float2*)(ob + (size_t)(r + 8) * NN + col) = o1;
        }
    }
}

// ---------------------------------------------------------------------------
extern "C" void kernel_launch(void* const* d_in, const int* in_sizes, int n_in,
                              void* d_out, int out_size)
{
    const float* x     = (const float*)d_in[0];
    const float* mask  = (const float*)d_in[1];
    const float* Wq    = (const float*)d_in[2];
    const float* Wk    = (const float*)d_in[3];
    const float* Wv    = (const float*)d_in[4];
    const float* gamma = (const float*)d_in[5];
    float* out = (float*)d_out;

    static bool attr_set = false;
    if (!attr_set) {
        cudaFuncSetAttribute(qkv_h_gemm, cudaFuncAttributeMaxDynamicSharedMemorySize, DSMEM32);
        cudaFuncSetAttribute(out_gemm_t, cudaFuncAttributeMaxDynamicSharedMemorySize, DSMEM32);
        attr_set = true;
    }

    round_x_kernel <<<(size_t)BB * CC * NN / (256 * 4), 256>>>(x);
    round_wv_kernel<<<(size_t)CC * CC / (256 * 4), 256>>>(Wv);
    qkv_fg_gemm<<<dim3(NN / 128, 1, BB), 256>>>(x, Wq, Wk);
    qkv_h_gemm<<<dim3(NN / 128, CC / 128, BB), 256, DSMEM32>>>(mask);
    scores_gemm_t<<<dim3(NN / 128, NN / 128, BB), 256>>>(mask);
    reduce_sums<<<dim3(NN / 256, BB), 256>>>();
    out_gemm_t<<<dim3(NN / 128, CC / 128, BB), 256, DSMEM32>>>(x, mask, gamma, out);
}

// round 11
// speedup vs baseline: 1.7486x; 1.2591x over previous
#include <cuda_runtime.h>
#include <cstdint>

// Problem dims (fixed by the dataset)
#define BB   64
#define CC   512
#define NN   1024
#define CQ   64
#define RTOT 640

// Scratch
__device__ float d_Y[(size_t)BB * RTOT * NN];        // f/g rows 0..127, h' rows 128..639
__device__ float d_scores[(size_t)BB * NN * NN];     // E = exp(leaky(scores)), tf32-rounded
__device__ float d_xr[(size_t)BB * CC * NN];         // x rounded to tf32 (rna)
__device__ float d_Wvr[(size_t)CC * CC];             // Wv rounded to tf32 (rna)
__device__ float d_partZ[(size_t)BB * 8 * NN];
__device__ float d_partSm[(size_t)BB * 8 * NN];
__device__ float d_colZ[(size_t)BB * NN];
__device__ float d_colSm[(size_t)BB * NN];

// ---------------------------------------------------------------------------
// helpers
// ---------------------------------------------------------------------------
__device__ __forceinline__ uint32_t f2tf(float f) {
    uint32_t u;
    asm("cvt.rna.tf32.f32 %0, %1;" : "=r"(u) : "f"(f));
    return u;
}

__device__ __forceinline__ void mma8(float4& d, const uint32_t a[4], const uint32_t b[2]) {
    asm volatile(
        "mma.sync.aligned.m16n8k8.row.col.f32.tf32.tf32.f32 "
        "{%0,%1,%2,%3}, {%4,%5,%6,%7}, {%8,%9}, {%0,%1,%2,%3};"
        : "+f"(d.x), "+f"(d.y), "+f"(d.z), "+f"(d.w)
        : "r"(a[0]), "r"(a[1]), "r"(a[2]), "r"(a[3]), "r"(b[0]), "r"(b[1]));
}

__device__ __forceinline__ void cp16(void* dst_smem, const void* src_gmem) {
    uint32_t d = (uint32_t)__cvta_generic_to_shared(dst_smem);
    asm volatile("cp.async.cg.shared.global [%0], [%1], 16;" :: "r"(d), "l"(src_gmem));
}
#define CP_COMMIT() asm volatile("cp.async.commit_group;")
#define CP_WAIT0()  asm volatile("cp.async.wait_group 0;")

// ---------------------------------------------------------------------------
// Inner compute variants over one 128x128x16 chunk (round-6 proven).
// A m-major [128][20]: lane addr = 20*gid + tig (mod 32) -> conflict-free.
// A k-major [16][136] / B [16][136]: lane addr = 8*tig + gid -> conflict-free.
// ---------------------------------------------------------------------------
__device__ __forceinline__ void compute_raw(
    const float (*As)[20], const float (*Bs)[136],
    float4 (&c)[4][4], int gid, int tig, int mw, int nw)
{
#pragma unroll
    for (int ks = 0; ks < 16; ks += 8) {
        uint32_t a[4][4], bfr[4][2];
#pragma unroll
        for (int f = 0; f < 4; f++) {
            const int r = mw + f * 16 + gid;
            a[f][0] = __float_as_uint(As[r][ks + tig]);
            a[f][1] = __float_as_uint(As[r + 8][ks + tig]);
            a[f][2] = __float_as_uint(As[r][ks + tig + 4]);
            a[f][3] = __float_as_uint(As[r + 8][ks + tig + 4]);
        }
#pragma unroll
        for (int g = 0; g < 4; g++) {
            const int n0 = nw + g * 8 + gid;
            bfr[g][0] = __float_as_uint(Bs[ks + tig][n0]);
            bfr[g][1] = __float_as_uint(Bs[ks + tig + 4][n0]);
        }
#pragma unroll
        for (int f = 0; f < 4; f++)
#pragma unroll
            for (int g = 0; g < 4; g++)
                mma8(c[f][g], a[f], bfr[g]);
    }
}

__device__ __forceinline__ void compute_split_mA(
    const float (*As)[20], const float (*Bs)[136],
    float4 (&c)[4][4], int gid, int tig, int mw, int nw)
{
#pragma unroll
    for (int ks = 0; ks < 16; ks += 8) {
        uint32_t ahi[4][4], alo[4][4];
        uint32_t bhi[4][2], blo[4][2];
#pragma unroll
        for (int f = 0; f < 4; f++) {
            const int r = mw + f * 16 + gid;
            float a0 = As[r][ks + tig];
            float a1 = As[r + 8][ks + tig];
            float a2 = As[r][ks + tig + 4];
            float a3 = As[r + 8][ks + tig + 4];
            ahi[f][0] = f2tf(a0); ahi[f][1] = f2tf(a1);
            ahi[f][2] = f2tf(a2); ahi[f][3] = f2tf(a3);
            alo[f][0] = f2tf(a0 - __uint_as_float(ahi[f][0]));
            alo[f][1] = f2tf(a1 - __uint_as_float(ahi[f][1]));
            alo[f][2] = f2tf(a2 - __uint_as_float(ahi[f][2]));
            alo[f][3] = f2tf(a3 - __uint_as_float(ahi[f][3]));
        }
#pragma unroll
        for (int g = 0; g < 4; g++) {
            const int n0 = nw + g * 8 + gid;
            float b0 = Bs[ks + tig][n0];
            float b1 = Bs[ks + tig + 4][n0];
            bhi[g][0] = f2tf(b0); bhi[g][1] = f2tf(b1);
            blo[g][0] = f2tf(b0 - __uint_as_float(bhi[g][0]));
            blo[g][1] = f2tf(b1 - __uint_as_float(bhi[g][1]));
        }
#pragma unroll
        for (int f = 0; f < 4; f++)
#pragma unroll
            for (int g = 0; g < 4; g++) {
                mma8(c[f][g], ahi[f], blo[g]);
                mma8(c[f][g], alo[f], bhi[g]);
                mma8(c[f][g], ahi[f], bhi[g]);
            }
    }
}

__device__ __forceinline__ void compute_split_kA(
    const float (*As)[136], const float (*Bs)[136],
    float4 (&c)[4][4], int gid, int tig, int mw, int nw)
{
#pragma unroll
    for (int ks = 0; ks < 16; ks += 8) {
        uint32_t ahi[4][4], alo[4][4];
        uint32_t bhi[4][2], blo[4][2];
#pragma unroll
        for (int f = 0; f < 4; f++) {
            const int r = mw + f * 16 + gid;
            float a0 = As[ks + tig][r];
            float a1 = As[ks + tig][r + 8];
            float a2 = As[ks + tig + 4][r];
            float a3 = As[ks + tig + 4][r + 8];
            ahi[f][0] = f2tf(a0); ahi[f][1] = f2tf(a1);
            ahi[f][2] = f2tf(a2); ahi[f][3] = f2tf(a3);
            alo[f][0] = f2tf(a0 - __uint_as_float(ahi[f][0]));
            alo[f][1] = f2tf(a1 - __uint_as_float(ahi[f][1]));
            alo[f][2] = f2tf(a2 - __uint_as_float(ahi[f][2]));
            alo[f][3] = f2tf(a3 - __uint_as_float(ahi[f][3]));
        }
#pragma unroll
        for (int g = 0; g < 4; g++) {
            const int n0 = nw + g * 8 + gid;
            float b0 = Bs[ks + tig][n0];
            float b1 = Bs[ks + tig + 4][n0];
            bhi[g][0] = f2tf(b0); bhi[g][1] = f2tf(b1);
            blo[g][0] = f2tf(b0 - __uint_as_float(bhi[g][0]));
            blo[g][1] = f2tf(b1 - __uint_as_float(bhi[g][1]));
        }
#pragma unroll
        for (int f = 0; f < 4; f++)
#pragma unroll
            for (int g = 0; g < 4; g++) {
                mma8(c[f][g], ahi[f], blo[g]);
                mma8(c[f][g], alo[f], bhi[g]);
                mma8(c[f][g], ahi[f], bhi[g]);
            }
    }
}

// ---------------------------------------------------------------------------
// K0: round x and Wv to tf32 (rna) once.
// ---------------------------------------------------------------------------
__global__ __launch_bounds__(256) void round_x_kernel(const float* __restrict__ x)
{
    const size_t i = ((size_t)blockIdx.x * 256 + threadIdx.x) * 4;
    float4 v = *(const float4*)(x + i);
    v.x = __uint_as_float(f2tf(v.x));
    v.y = __uint_as_float(f2tf(v.y));
    v.z = __uint_as_float(f2tf(v.z));
    v.w = __uint_as_float(f2tf(v.w));
    *(float4*)(d_xr + i) = v;
}

__global__ __launch_bounds__(256) void round_wv_kernel(const float* __restrict__ Wv)
{
    const size_t i = ((size_t)blockIdx.x * 256 + threadIdx.x) * 4;
    float4 v = *(const float4*)(Wv + i);
    v.x = __uint_as_float(f2tf(v.x));
    v.y = __uint_as_float(f2tf(v.y));
    v.z = __uint_as_float(f2tf(v.z));
    v.w = __uint_as_float(f2tf(v.w));
    *(float4*)(d_Wvr + i) = v;
}

// ---------------------------------------------------------------------------
// K1a: f,g projection = [Wq;Wk] @ x.  SPLIT tf32, cp.async. (round-6 proven)
// ---------------------------------------------------------------------------
__global__ __launch_bounds__(256) void qkv_fg_gemm(
    const float* __restrict__ x,
    const float* __restrict__ Wq,
    const float* __restrict__ Wk)
{
    __shared__ float As[2][128][20];
    __shared__ float Bs[2][16][136];

    const int b = blockIdx.z;
    const int col0 = blockIdx.x * 128;
    const float* xb = x + (size_t)b * CC * NN;

    const int tid = threadIdx.x, lane = tid & 31, warp = tid >> 5;
    const int gid = lane >> 2, tig = lane & 3;
    const int mw = (warp >> 2) * 64, nw = (warp & 3) * 32;

    const int am0 = tid >> 2;
    const int ak  = (tid & 3) * 4;
    const float* arow0 = Wq + (size_t)am0 * CC;
    const float* arow1 = Wk + (size_t)am0 * CC;
    const int bk0 = tid >> 5;
    const int bn  = (tid & 31) * 4;

    float4 c[4][4];
#pragma unroll
    for (int f = 0; f < 4; f++)
#pragma unroll
        for (int g = 0; g < 4; g++) c[f][g] = make_float4(0, 0, 0, 0);

    cp16(&As[0][am0][ak],       arow0 + ak);
    cp16(&As[0][am0 + 64][ak],  arow1 + ak);
    cp16(&Bs[0][bk0][bn],       xb + (size_t)bk0 * NN + col0 + bn);
    cp16(&Bs[0][bk0 + 8][bn],   xb + (size_t)(bk0 + 8) * NN + col0 + bn);
    CP_COMMIT();
    CP_WAIT0();
    __syncthreads();

    const int NS = CC / 16;
    for (int s = 0; s < NS; s++) {
        const int buf = s & 1;
        if (s + 1 < NS) {
            const int kc = (s + 1) * 16;
            const int nb = buf ^ 1;
            cp16(&As[nb][am0][ak],      arow0 + kc + ak);
            cp16(&As[nb][am0 + 64][ak], arow1 + kc + ak);
            cp16(&Bs[nb][bk0][bn],      xb + (size_t)(kc + bk0) * NN + col0 + bn);
            cp16(&Bs[nb][bk0 + 8][bn],  xb + (size_t)(kc + bk0 + 8) * NN + col0 + bn);
            CP_COMMIT();
        }
        compute_split_mA(As[buf], Bs[buf], c, gid, tig, mw, nw);
        CP_WAIT0();
        __syncthreads();
    }

    float* yb = d_Y + (size_t)b * RTOT * NN;
#pragma unroll
    for (int f = 0; f < 4; f++) {
        const int r = mw + f * 16 + gid;
#pragma unroll
        for (int g = 0; g < 4; g++) {
            const int col = col0 + nw + g * 8 + 2 * tig;
            *(float2*)(yb + (size_t)r * NN + col)       = make_float2(c[f][g].x, c[f][g].y);
            *(float2*)(yb + (size_t)(r + 8) * NN + col) = make_float2(c[f][g].z, c[f][g].w);
        }
    }
}

// ---------------------------------------------------------------------------
// K1b: h' = (Wvr @ xr) * mask[col], tf32-rounded on store. (round-6 proven)
// ---------------------------------------------------------------------------
__global__ __launch_bounds__(256) void qkv_h_gemm(const float* __restrict__ mask)
{
    __shared__ float As[2][128][20];
    __shared__ float Bs[2][16][136];

    const int b = blockIdx.z;
    const int row0 = blockIdx.y * 128;
    const int col0 = blockIdx.x * 128;
    const float* xb = d_xr + (size_t)b * CC * NN;

    const int tid = threadIdx.x, lane = tid & 31, warp = tid >> 5;
    const int gid = lane >> 2, tig = lane & 3;
    const int mw = (warp >> 2) * 64, nw = (warp & 3) * 32;

    const int am0 = tid >> 2;
    const int ak  = (tid & 3) * 4;
    const float* arow0 = d_Wvr + (size_t)(row0 + am0) * CC;
    const float* arow1 = d_Wvr + (size_t)(row0 + am0 + 64) * CC;
    const int bk0 = tid >> 5;
    const int bn  = (tid & 31) * 4;

    float4 c[4][4];
#pragma unroll
    for (int f = 0; f < 4; f++)
#pragma unroll
        for (int g = 0; g < 4; g++) c[f][g] = make_float4(0, 0, 0, 0);

    cp16(&As[0][am0][ak],      arow0 + ak);
    cp16(&As[0][am0 + 64][ak], arow1 + ak);
    cp16(&Bs[0][bk0][bn],      xb + (size_t)bk0 * NN + col0 + bn);
    cp16(&Bs[0][bk0 + 8][bn],  xb + (size_t)(bk0 + 8) * NN + col0 + bn);
    CP_COMMIT();
    CP_WAIT0();
    __syncthreads();

    const int NS = CC / 16;
    for (int s = 0; s < NS; s++) {
        const int buf = s & 1;
        if (s + 1 < NS) {
            const int kc = (s + 1) * 16;
            const int nb = buf ^ 1;
            cp16(&As[nb][am0][ak],      arow0 + kc + ak);
            cp16(&As[nb][am0 + 64][ak], arow1 + kc + ak);
            cp16(&Bs[nb][bk0][bn],      xb + (size_t)(kc + bk0) * NN + col0 + bn);
            cp16(&Bs[nb][bk0 + 8][bn],  xb + (size_t)(kc + bk0 + 8) * NN + col0 + bn);
            CP_COMMIT();
        }
        compute_raw(As[buf], Bs[buf], c, gid, tig, mw, nw);
        CP_WAIT0();
        __syncthreads();
    }

    float* yb = d_Y + (size_t)b * RTOT * NN + (size_t)(2 * CQ + row0) * NN;
    const float* mb = mask + (size_t)b * NN;
#pragma unroll
    for (int f = 0; f < 4; f++) {
        const int r = mw + f * 16 + gid;
#pragma unroll
        for (int g = 0; g < 4; g++) {
            const int col = col0 + nw + g * 8 + 2 * tig;
            float2 mv = *(const float2*)(mb + col);
            float2 o0, o1;
            o0.x = __uint_as_float(f2tf(c[f][g].x * mv.x));
            o0.y = __uint_as_float(f2tf(c[f][g].y * mv.y));
            o1.x = __uint_as_float(f2tf(c[f][g].z * mv.x));
            o1.y = __uint_as_float(f2tf(c[f][g].w * mv.y));
            *(float2*)(yb + (size_t)r * NN + col)       = o0;
            *(float2*)(yb + (size_t)(r + 8) * NN + col) = o1;
        }
    }
}

// ---------------------------------------------------------------------------
// K2: E = tf32_round(exp(leaky(F^T G))), K=64, SPLIT tf32, cp.async.
// Emits per-i-tile column partial sums of Z and mask*E. (round-6 proven)
// ---------------------------------------------------------------------------
__global__ __launch_bounds__(256) void scores_gemm_t(const float* __restrict__ mask)
{
    __shared__ float As[2][16][136];
    __shared__ float Bs[2][16][136];
    __shared__ float sZ[128];
    __shared__ float sSm[128];

    const int b  = blockIdx.z;
    const int it = blockIdx.y;
    const int i0 = it * 128;
    const int j0 = blockIdx.x * 128;
    const float* F = d_Y + (size_t)b * RTOT * NN;
    const float* G = F + (size_t)CQ * NN;

    const int tid = threadIdx.x, lane = tid & 31, warp = tid >> 5;
    const int gid = lane >> 2, tig = lane & 3;
    const int mw = (warp >> 2) * 64, nw = (warp & 3) * 32;
    const int bk0 = tid >> 5;
    const int bn  = (tid & 31) * 4;

    if (tid < 128) { sZ[tid] = 0.0f; sSm[tid] = 0.0f; }

    float4 c[4][4];
#pragma unroll
    for (int f = 0; f < 4; f++)
#pragma unroll
        for (int g = 0; g < 4; g++) c[f][g] = make_float4(0, 0, 0, 0);

    cp16(&As[0][bk0][bn],     F + (size_t)bk0 * NN + i0 + bn);
    cp16(&As[0][bk0 + 8][bn], F + (size_t)(bk0 + 8) * NN + i0 + bn);
    cp16(&Bs[0][bk0][bn],     G + (size_t)bk0 * NN + j0 + bn);
    cp16(&Bs[0][bk0 + 8][bn], G + (size_t)(bk0 + 8) * NN + j0 + bn);
    CP_COMMIT();
    CP_WAIT0();
    __syncthreads();

    const int NS = CQ / 16;  // 4
    for (int s = 0; s < NS; s++) {
        const int buf = s & 1;
        if (s + 1 < NS) {
            const int kc = (s + 1) * 16;
            const int nb = buf ^ 1;
            cp16(&As[nb][bk0][bn],     F + (size_t)(kc + bk0) * NN + i0 + bn);
            cp16(&As[nb][bk0 + 8][bn], F + (size_t)(kc + bk0 + 8) * NN + i0 + bn);
            cp16(&Bs[nb][bk0][bn],     G + (size_t)(kc + bk0) * NN + j0 + bn);
            cp16(&Bs[nb][bk0 + 8][bn], G + (size_t)(kc + bk0 + 8) * NN + j0 + bn);
            CP_COMMIT();
        }
        compute_split_kA(As[buf], Bs[buf], c, gid, tig, mw, nw);
        CP_WAIT0();
        __syncthreads();
    }

    float* S = d_scores + (size_t)b * NN * NN;
    const float* mb = mask + (size_t)b * NN;

    float mrow[4][2];
#pragma unroll
    for (int f = 0; f < 4; f++) {
        const int r = i0 + mw + f * 16 + gid;
        mrow[f][0] = __ldg(&mb[r]);
        mrow[f][1] = __ldg(&mb[r + 8]);
    }

#pragma unroll
    for (int g = 0; g < 4; g++) {
        const int colL = nw + g * 8 + 2 * tig;
        float z0 = 0, z1 = 0, sm0 = 0, sm1 = 0;
#pragma unroll
        for (int f = 0; f < 4; f++) {
            const int r = i0 + mw + f * 16 + gid;
            float s0 = c[f][g].x, s1 = c[f][g].y, s2 = c[f][g].z, s3 = c[f][g].w;
            s0 = s0 >= 0.0f ? s0 : 0.2f * s0;
            s1 = s1 >= 0.0f ? s1 : 0.2f * s1;
            s2 = s2 >= 0.0f ? s2 : 0.2f * s2;
            s3 = s3 >= 0.0f ? s3 : 0.2f * s3;
            float e0 = __expf(fminf(s0, 75.0f));
            float e1 = __expf(fminf(s1, 75.0f));
            float e2 = __expf(fminf(s2, 75.0f));
            float e3 = __expf(fminf(s3, 75.0f));
            *(float2*)(S + (size_t)r * NN + j0 + colL) =
                make_float2(__uint_as_float(f2tf(e0)), __uint_as_float(f2tf(e1)));
            *(float2*)(S + (size_t)(r + 8) * NN + j0 + colL) =
                make_float2(__uint_as_float(f2tf(e2)), __uint_as_float(f2tf(e3)));
            z0 += e0 + e2;   z1 += e1 + e3;
            sm0 += mrow[f][0] * e0 + mrow[f][1] * e2;
            sm1 += mrow[f][0] * e1 + mrow[f][1] * e3;
        }
        atomicAdd(&sZ[colL], z0);       atomicAdd(&sZ[colL + 1], z1);
        atomicAdd(&sSm[colL], sm0);     atomicAdd(&sSm[colL + 1], sm1);
    }
    __syncthreads();
    if (tid < 128) {
        const size_t off = ((size_t)b * 8 + it) * NN + j0 + tid;
        d_partZ[off]  = sZ[tid];
        d_partSm[off] = sSm[tid];
    }
}

// ---------------------------------------------------------------------------
// K2b: fold 8 i-tile partials into column sums.
// ---------------------------------------------------------------------------
__global__ __launch_bounds__(256) void reduce_sums()
{
    const int b = blockIdx.y;
    const int j = blockIdx.x * 256 + threadIdx.x;
    float z = 0.0f, s = 0.0f;
#pragma unroll
    for (int t = 0; t < 8; t++) {
        const size_t off = ((size_t)b * 8 + t) * NN + j;
        z += d_partZ[off];
        s += d_partSm[off];
    }
    d_colZ[(size_t)b * NN + j]  = z;
    d_colSm[(size_t)b * NN + j] = s;
}

// ---------------------------------------------------------------------------
// K4: out[c][m] = gamma*(sum_n h'[c][n]*E[n][m])*mask[m]/(Sm+eps*Z) + x[c][m]
// Raw MMA, cp.async. (round-6 proven)
// ---------------------------------------------------------------------------
__global__ __launch_bounds__(256) void out_gemm_t(
    const float* __restrict__ x,
    const float* __restrict__ mask,
    const float* __restrict__ gamma,
    float* __restrict__ out)
{
    __shared__ float As[2][128][20];
    __shared__ float Bs[2][16][136];

    const int b  = blockIdx.z;
    const int c0 = blockIdx.y * 128;
    const int m0 = blockIdx.x * 128;
    const float* h  = d_Y + (size_t)b * RTOT * NN + (size_t)(2 * CQ) * NN;
    const float* Bt = d_scores + (size_t)b * NN * NN;

    const int tid = threadIdx.x, lane = tid & 31, warp = tid >> 5;
    const int gid = lane >> 2, tig = lane & 3;
    const int mw = (warp >> 2) * 64, nw = (warp & 3) * 32;

    const int am0 = tid >> 2;
    const int ak  = (tid & 3) * 4;
    const float* arow0 = h + (size_t)(c0 + am0) * NN;
    const float* arow1 = h + (size_t)(c0 + am0 + 64) * NN;
    const int bk0 = tid >> 5;
    const int bn  = (tid & 31) * 4;

    float4 c[4][4];
#pragma unroll
    for (int f = 0; f < 4; f++)
#pragma unroll
        for (int g = 0; g < 4; g++) c[f][g] = make_float4(0, 0, 0, 0);

    cp16(&As[0][am0][ak],      arow0 + ak);
    cp16(&As[0][am0 + 64][ak], arow1 + ak);
    cp16(&Bs[0][bk0][bn],      Bt + (size_t)bk0 * NN + m0 + bn);
    cp16(&Bs[0][bk0 + 8][bn],  Bt + (size_t)(bk0 + 8) * NN + m0 + bn);
    CP_COMMIT();
    CP_WAIT0();
    __syncthreads();

    const int NS = NN / 16;  // 64
    for (int s = 0; s < NS; s++) {
        const int buf = s & 1;
        if (s + 1 < NS) {
            const int kc = (s + 1) * 16;
            const int nb = buf ^ 1;
            cp16(&As[nb][am0][ak],      arow0 + kc + ak);
            cp16(&As[nb][am0 + 64][ak], arow1 + kc + ak);
            cp16(&Bs[nb][bk0][bn],      Bt + (size_t)(kc + bk0) * NN + m0 + bn);
            cp16(&Bs[nb][bk0 + 8][bn],  Bt + (size_t)(kc + bk0 + 8) * NN + m0 + bn);
            CP_COMMIT();
        }
        compute_raw(As[buf], Bs[buf], c, gid, tig, mw, nw);
        CP_WAIT0();
        __syncthreads();
    }

    const float g0 = gamma[0];
    const float* xb = x + (size_t)b * CC * NN;
    float* ob = out + (size_t)b * CC * NN;
    const float* mb = mask + (size_t)b * NN;
    const float* zc = d_colZ + (size_t)b * NN;
    const float* sc = d_colSm + (size_t)b * NN;

#pragma unroll
    for (int g = 0; g < 4; g++) {
        const int col = m0 + nw + g * 8 + 2 * tig;
        float2 mv = *(const float2*)(mb + col);
        float2 zv = *(const float2*)(zc + col);
        float2 sv = *(const float2*)(sc + col);
        const float w0 = g0 * mv.x / (sv.x + 1e-6f * zv.x);
        const float w1 = g0 * mv.y / (sv.y + 1e-6f * zv.y);
#pragma unroll
        for (int f = 0; f < 4; f++) {
            const int r = c0 + mw + f * 16 + gid;
            float2 x0 = *(const float2*)(xb + (size_t)r * NN + col);
            float2 x1 = *(const float2*)(xb + (size_t)(r + 8) * NN + col);
            float2 o0, o1;
            o0.x = c[f][g].x * w0 + x0.x;
            o0.y = c[f][g].y * w1 + x0.y;
            o1.x = c[f][g].z * w0 + x1.x;
            o1.y = c[f][g].w * w1 + x1.y;
            *(float2*)(ob + (size_t)r * NN + col)       = o0;
            *(float2*)(ob + (size_t)(r + 8) * NN + col) = o1;
        }
    }
}

// ---------------------------------------------------------------------------
// Launch: fork the independent h'-chain onto a second stream so it overlaps
// the fg -> scores -> reduce chain; join before out_gemm.
//   stream 0 (capture stream): fg -> scores -> reduce -> [wait evJoin] -> out
//   stream s2:                 [wait evFork] round_x, round_wv, qkv_h -> evJoin
// Disjoint data: qkv_h writes d_Y rows 128..639; scores reads rows 0..127 only.
// ---------------------------------------------------------------------------
extern "C" void kernel_launch(void* const* d_in, const int* in_sizes, int n_in,
                              void* d_out, int out_size)
{
    const float* x     = (const float*)d_in[0];
    const float* mask  = (const float*)d_in[1];
    const float* Wq    = (const float*)d_in[2];
    const float* Wk    = (const float*)d_in[3];
    const float* Wv    = (const float*)d_in[4];
    const float* gamma = (const float*)d_in[5];
    float* out = (float*)d_out;

    static cudaStream_t s2 = nullptr;
    static cudaEvent_t evFork = nullptr, evJoin = nullptr;
    if (s2 == nullptr) {
        cudaStreamCreateWithFlags(&s2, cudaStreamNonBlocking);
        cudaEventCreateWithFlags(&evFork, cudaEventDisableTiming);
        cudaEventCreateWithFlags(&evJoin, cudaEventDisableTiming);
    }

    // fork
    cudaEventRecord(evFork, 0);
    cudaStreamWaitEvent(s2, evFork, 0);

    // stream s2: h' chain
    round_x_kernel <<<(size_t)BB * CC * NN / (256 * 4), 256, 0, s2>>>(x);
    round_wv_kernel<<<(size_t)CC * CC / (256 * 4), 256, 0, s2>>>(Wv);
    qkv_h_gemm<<<dim3(NN / 128, CC / 128, BB), 256, 0, s2>>>(mask);
    cudaEventRecord(evJoin, s2);

    // stream 0: fg -> scores -> reduce
    qkv_fg_gemm<<<dim3(NN / 128, 1, BB), 256>>>(x, Wq, Wk);
    scores_gemm_t<<<dim3(NN / 128, NN / 128, BB), 256>>>(mask);
    reduce_sums<<<dim3(NN / 256, BB), 256>>>();

    // join, then the output GEMM
    cudaStreamWaitEvent(0, evJoin, 0);
    out_gemm_t<<<dim3(NN / 128, CC / 128, BB), 256>>>(x, mask, gamma, out);
}

// round 13
// speedup vs baseline: 1.7985x; 1.0286x over previous
#include <cuda_runtime.h>
#include <cstdint>

// Problem dims (fixed by the dataset)
#define BB   64
#define CC   512
#define NN   1024
#define CQ   64
#define RTOT 640

// Scratch
__device__ float d_Y[(size_t)BB * RTOT * NN];        // f/g rows 0..127, h' rows 128..639
__device__ float d_scores[(size_t)BB * NN * NN];     // E = exp(leaky(scores)), tf32-rounded
__device__ float d_xr[(size_t)BB * CC * NN];         // x rounded to tf32 (rna)
__device__ float d_Wvr[(size_t)CC * CC];             // Wv rounded to tf32 (rna)
__device__ float d_partZ[(size_t)BB * 8 * NN];
__device__ float d_partSm[(size_t)BB * 8 * NN];
__device__ float d_colZ[(size_t)BB * NN];
__device__ float d_colSm[(size_t)BB * NN];

// ---------------------------------------------------------------------------
// helpers
// ---------------------------------------------------------------------------
__device__ __forceinline__ uint32_t f2tf(float f) {
    uint32_t u;
    asm("cvt.rna.tf32.f32 %0, %1;" : "=r"(u) : "f"(f));
    return u;
}

__device__ __forceinline__ void mma8(float4& d, const uint32_t a[4], const uint32_t b[2]) {
    asm volatile(
        "mma.sync.aligned.m16n8k8.row.col.f32.tf32.tf32.f32 "
        "{%0,%1,%2,%3}, {%4,%5,%6,%7}, {%8,%9}, {%0,%1,%2,%3};"
        : "+f"(d.x), "+f"(d.y), "+f"(d.z), "+f"(d.w)
        : "r"(a[0]), "r"(a[1]), "r"(a[2]), "r"(a[3]), "r"(b[0]), "r"(b[1]));
}

__device__ __forceinline__ void cp16(void* dst_smem, const void* src_gmem) {
    uint32_t d = (uint32_t)__cvta_generic_to_shared(dst_smem);
    asm volatile("cp.async.cg.shared.global [%0], [%1], 16;" :: "r"(d), "l"(src_gmem));
}
#define CP_COMMIT() asm volatile("cp.async.commit_group;")
#define CP_WAIT0()  asm volatile("cp.async.wait_group 0;")

// ---------------------------------------------------------------------------
// Inner compute variants over one 128x128x16 chunk (round-6 proven).
// A m-major [128][20]: lane addr = 20*gid + tig (mod 32) -> conflict-free.
// A k-major [16][136] / B [16][136]: lane addr = 8*tig + gid -> conflict-free.
// ---------------------------------------------------------------------------
__device__ __forceinline__ void compute_raw(
    const float (*As)[20], const float (*Bs)[136],
    float4 (&c)[4][4], int gid, int tig, int mw, int nw)
{
#pragma unroll
    for (int ks = 0; ks < 16; ks += 8) {
        uint32_t a[4][4], bfr[4][2];
#pragma unroll
        for (int f = 0; f < 4; f++) {
            const int r = mw + f * 16 + gid;
            a[f][0] = __float_as_uint(As[r][ks + tig]);
            a[f][1] = __float_as_uint(As[r + 8][ks + tig]);
            a[f][2] = __float_as_uint(As[r][ks + tig + 4]);
            a[f][3] = __float_as_uint(As[r + 8][ks + tig + 4]);
        }
#pragma unroll
        for (int g = 0; g < 4; g++) {
            const int n0 = nw + g * 8 + gid;
            bfr[g][0] = __float_as_uint(Bs[ks + tig][n0]);
            bfr[g][1] = __float_as_uint(Bs[ks + tig + 4][n0]);
        }
#pragma unroll
        for (int f = 0; f < 4; f++)
#pragma unroll
            for (int g = 0; g < 4; g++)
                mma8(c[f][g], a[f], bfr[g]);
    }
}

__device__ __forceinline__ void compute_split_mA(
    const float (*As)[20], const float (*Bs)[136],
    float4 (&c)[4][4], int gid, int tig, int mw, int nw)
{
#pragma unroll
    for (int ks = 0; ks < 16; ks += 8) {
        uint32_t ahi[4][4], alo[4][4];
        uint32_t bhi[4][2], blo[4][2];
#pragma unroll
        for (int f = 0; f < 4; f++) {
            const int r = mw + f * 16 + gid;
            float a0 = As[r][ks + tig];
            float a1 = As[r + 8][ks + tig];
            float a2 = As[r][ks + tig + 4];
            float a3 = As[r + 8][ks + tig + 4];
            ahi[f][0] = f2tf(a0); ahi[f][1] = f2tf(a1);
            ahi[f][2] = f2tf(a2); ahi[f][3] = f2tf(a3);
            alo[f][0] = f2tf(a0 - __uint_as_float(ahi[f][0]));
            alo[f][1] = f2tf(a1 - __uint_as_float(ahi[f][1]));
            alo[f][2] = f2tf(a2 - __uint_as_float(ahi[f][2]));
            alo[f][3] = f2tf(a3 - __uint_as_float(ahi[f][3]));
        }
#pragma unroll
        for (int g = 0; g < 4; g++) {
            const int n0 = nw + g * 8 + gid;
            float b0 = Bs[ks + tig][n0];
            float b1 = Bs[ks + tig + 4][n0];
            bhi[g][0] = f2tf(b0); bhi[g][1] = f2tf(b1);
            blo[g][0] = f2tf(b0 - __uint_as_float(bhi[g][0]));
            blo[g][1] = f2tf(b1 - __uint_as_float(bhi[g][1]));
        }
#pragma unroll
        for (int f = 0; f < 4; f++)
#pragma unroll
            for (int g = 0; g < 4; g++) {
                mma8(c[f][g], ahi[f], blo[g]);
                mma8(c[f][g], alo[f], bhi[g]);
                mma8(c[f][g], ahi[f], bhi[g]);
            }
    }
}

__device__ __forceinline__ void compute_split_kA(
    const float (*As)[136], const float (*Bs)[136],
    float4 (&c)[4][4], int gid, int tig, int mw, int nw)
{
#pragma unroll
    for (int ks = 0; ks < 16; ks += 8) {
        uint32_t ahi[4][4], alo[4][4];
        uint32_t bhi[4][2], blo[4][2];
#pragma unroll
        for (int f = 0; f < 4; f++) {
            const int r = mw + f * 16 + gid;
            float a0 = As[ks + tig][r];
            float a1 = As[ks + tig][r + 8];
            float a2 = As[ks + tig + 4][r];
            float a3 = As[ks + tig + 4][r + 8];
            ahi[f][0] = f2tf(a0); ahi[f][1] = f2tf(a1);
            ahi[f][2] = f2tf(a2); ahi[f][3] = f2tf(a3);
            alo[f][0] = f2tf(a0 - __uint_as_float(ahi[f][0]));
            alo[f][1] = f2tf(a1 - __uint_as_float(ahi[f][1]));
            alo[f][2] = f2tf(a2 - __uint_as_float(ahi[f][2]));
            alo[f][3] = f2tf(a3 - __uint_as_float(ahi[f][3]));
        }
#pragma unroll
        for (int g = 0; g < 4; g++) {
            const int n0 = nw + g * 8 + gid;
            float b0 = Bs[ks + tig][n0];
            float b1 = Bs[ks + tig + 4][n0];
            bhi[g][0] = f2tf(b0); bhi[g][1] = f2tf(b1);
            blo[g][0] = f2tf(b0 - __uint_as_float(bhi[g][0]));
            blo[g][1] = f2tf(b1 - __uint_as_float(bhi[g][1]));
        }
#pragma unroll
        for (int f = 0; f < 4; f++)
#pragma unroll
            for (int g = 0; g < 4; g++) {
                mma8(c[f][g], ahi[f], blo[g]);
                mma8(c[f][g], alo[f], bhi[g]);
                mma8(c[f][g], ahi[f], bhi[g]);
            }
    }
}

// ---------------------------------------------------------------------------
// K0: round x and Wv to tf32 (rna) once.
// ---------------------------------------------------------------------------
__global__ __launch_bounds__(256) void round_x_kernel(const float* __restrict__ x)
{
    const size_t i = ((size_t)blockIdx.x * 256 + threadIdx.x) * 4;
    float4 v = *(const float4*)(x + i);
    v.x = __uint_as_float(f2tf(v.x));
    v.y = __uint_as_float(f2tf(v.y));
    v.z = __uint_as_float(f2tf(v.z));
    v.w = __uint_as_float(f2tf(v.w));
    *(float4*)(d_xr + i) = v;
}

__global__ __launch_bounds__(256) void round_wv_kernel(const float* __restrict__ Wv)
{
    const size_t i = ((size_t)blockIdx.x * 256 + threadIdx.x) * 4;
    float4 v = *(const float4*)(Wv + i);
    v.x = __uint_as_float(f2tf(v.x));
    v.y = __uint_as_float(f2tf(v.y));
    v.z = __uint_as_float(f2tf(v.z));
    v.w = __uint_as_float(f2tf(v.w));
    *(float4*)(d_Wvr + i) = v;
}

// ---------------------------------------------------------------------------
// K1a: f,g projection = [Wq;Wk] @ x.  SPLIT tf32, cp.async.
// __launch_bounds__(256, 2): cap regs at 128 so 2 CTAs co-reside per SM.
// ---------------------------------------------------------------------------
__global__ __launch_bounds__(256, 2) void qkv_fg_gemm(
    const float* __restrict__ x,
    const float* __restrict__ Wq,
    const float* __restrict__ Wk)
{
    __shared__ float As[2][128][20];
    __shared__ float Bs[2][16][136];

    const int b = blockIdx.z;
    const int col0 = blockIdx.x * 128;
    const float* xb = x + (size_t)b * CC * NN;

    const int tid = threadIdx.x, lane = tid & 31, warp = tid >> 5;
    const int gid = lane >> 2, tig = lane & 3;
    const int mw = (warp >> 2) * 64, nw = (warp & 3) * 32;

    const int am0 = tid >> 2;
    const int ak  = (tid & 3) * 4;
    const float* arow0 = Wq + (size_t)am0 * CC;
    const float* arow1 = Wk + (size_t)am0 * CC;
    const int bk0 = tid >> 5;
    const int bn  = (tid & 31) * 4;

    float4 c[4][4];
#pragma unroll
    for (int f = 0; f < 4; f++)
#pragma unroll
        for (int g = 0; g < 4; g++) c[f][g] = make_float4(0, 0, 0, 0);

    cp16(&As[0][am0][ak],       arow0 + ak);
    cp16(&As[0][am0 + 64][ak],  arow1 + ak);
    cp16(&Bs[0][bk0][bn],       xb + (size_t)bk0 * NN + col0 + bn);
    cp16(&Bs[0][bk0 + 8][bn],   xb + (size_t)(bk0 + 8) * NN + col0 + bn);
    CP_COMMIT();
    CP_WAIT0();
    __syncthreads();

    const int NS = CC / 16;
    for (int s = 0; s < NS; s++) {
        const int buf = s & 1;
        if (s + 1 < NS) {
            const int kc = (s + 1) * 16;
            const int nb = buf ^ 1;
            cp16(&As[nb][am0][ak],      arow0 + kc + ak);
            cp16(&As[nb][am0 + 64][ak], arow1 + kc + ak);
            cp16(&Bs[nb][bk0][bn],      xb + (size_t)(kc + bk0) * NN + col0 + bn);
            cp16(&Bs[nb][bk0 + 8][bn],  xb + (size_t)(kc + bk0 + 8) * NN + col0 + bn);
            CP_COMMIT();
        }
        compute_split_mA(As[buf], Bs[buf], c, gid, tig, mw, nw);
        CP_WAIT0();
        __syncthreads();
    }

    float* yb = d_Y + (size_t)b * RTOT * NN;
#pragma unroll
    for (int f = 0; f < 4; f++) {
        const int r = mw + f * 16 + gid;
#pragma unroll
        for (int g = 0; g < 4; g++) {
            const int col = col0 + nw + g * 8 + 2 * tig;
            *(float2*)(yb + (size_t)r * NN + col)       = make_float2(c[f][g].x, c[f][g].y);
            *(float2*)(yb + (size_t)(r + 8) * NN + col) = make_float2(c[f][g].z, c[f][g].w);
        }
    }
}

// ---------------------------------------------------------------------------
// K1b: h' = (Wvr @ xr) * mask[col], tf32-rounded on store. (round-6 proven)
// ---------------------------------------------------------------------------
__global__ __launch_bounds__(256, 2) void qkv_h_gemm(const float* __restrict__ mask)
{
    __shared__ float As[2][128][20];
    __shared__ float Bs[2][16][136];

    const int b = blockIdx.z;
    const int row0 = blockIdx.y * 128;
    const int col0 = blockIdx.x * 128;
    const float* xb = d_xr + (size_t)b * CC * NN;

    const int tid = threadIdx.x, lane = tid & 31, warp = tid >> 5;
    const int gid = lane >> 2, tig = lane & 3;
    const int mw = (warp >> 2) * 64, nw = (warp & 3) * 32;

    const int am0 = tid >> 2;
    const int ak  = (tid & 3) * 4;
    const float* arow0 = d_Wvr + (size_t)(row0 + am0) * CC;
    const float* arow1 = d_Wvr + (size_t)(row0 + am0 + 64) * CC;
    const int bk0 = tid >> 5;
    const int bn  = (tid & 31) * 4;

    float4 c[4][4];
#pragma unroll
    for (int f = 0; f < 4; f++)
#pragma unroll
        for (int g = 0; g < 4; g++) c[f][g] = make_float4(0, 0, 0, 0);

    cp16(&As[0][am0][ak],      arow0 + ak);
    cp16(&As[0][am0 + 64][ak], arow1 + ak);
    cp16(&Bs[0][bk0][bn],      xb + (size_t)bk0 * NN + col0 + bn);
    cp16(&Bs[0][bk0 + 8][bn],  xb + (size_t)(bk0 + 8) * NN + col0 + bn);
    CP_COMMIT();
    CP_WAIT0();
    __syncthreads();

    const int NS = CC / 16;
    for (int s = 0; s < NS; s++) {
        const int buf = s & 1;
        if (s + 1 < NS) {
            const int kc = (s + 1) * 16;
            const int nb = buf ^ 1;
            cp16(&As[nb][am0][ak],      arow0 + kc + ak);
            cp16(&As[nb][am0 + 64][ak], arow1 + kc + ak);
            cp16(&Bs[nb][bk0][bn],      xb + (size_t)(kc + bk0) * NN + col0 + bn);
            cp16(&Bs[nb][bk0 + 8][bn],  xb + (size_t)(kc + bk0 + 8) * NN + col0 + bn);
            CP_COMMIT();
        }
        compute_raw(As[buf], Bs[buf], c, gid, tig, mw, nw);
        CP_WAIT0();
        __syncthreads();
    }

    float* yb = d_Y + (size_t)b * RTOT * NN + (size_t)(2 * CQ + row0) * NN;
    const float* mb = mask + (size_t)b * NN;
#pragma unroll
    for (int f = 0; f < 4; f++) {
        const int r = mw + f * 16 + gid;
#pragma unroll
        for (int g = 0; g < 4; g++) {
            const int col = col0 + nw + g * 8 + 2 * tig;
            float2 mv = *(const float2*)(mb + col);
            float2 o0, o1;
            o0.x = __uint_as_float(f2tf(c[f][g].x * mv.x));
            o0.y = __uint_as_float(f2tf(c[f][g].y * mv.y));
            o1.x = __uint_as_float(f2tf(c[f][g].z * mv.x));
            o1.y = __uint_as_float(f2tf(c[f][g].w * mv.y));
            *(float2*)(yb + (size_t)r * NN + col)       = o0;
            *(float2*)(yb + (size_t)(r + 8) * NN + col) = o1;
        }
    }
}

// ---------------------------------------------------------------------------
// K2: E = tf32_round(exp(leaky(F^T G))), K=64, SPLIT tf32, cp.async.
// __launch_bounds__(256, 2) for 2 CTAs/SM.
// ---------------------------------------------------------------------------
__global__ __launch_bounds__(256, 2) void scores_gemm_t(const float* __restrict__ mask)
{
    __shared__ float As[2][16][136];
    __shared__ float Bs[2][16][136];
    __shared__ float sZ[128];
    __shared__ float sSm[128];

    const int b  = blockIdx.z;
    const int it = blockIdx.y;
    const int i0 = it * 128;
    const int j0 = blockIdx.x * 128;
    const float* F = d_Y + (size_t)b * RTOT * NN;
    const float* G = F + (size_t)CQ * NN;

    const int tid = threadIdx.x, lane = tid & 31, warp = tid >> 5;
    const int gid = lane >> 2, tig = lane & 3;
    const int mw = (warp >> 2) * 64, nw = (warp & 3) * 32;
    const int bk0 = tid >> 5;
    const int bn  = (tid & 31) * 4;

    if (tid < 128) { sZ[tid] = 0.0f; sSm[tid] = 0.0f; }

    float4 c[4][4];
#pragma unroll
    for (int f = 0; f < 4; f++)
#pragma unroll
        for (int g = 0; g < 4; g++) c[f][g] = make_float4(0, 0, 0, 0);

    cp16(&As[0][bk0][bn],     F + (size_t)bk0 * NN + i0 + bn);
    cp16(&As[0][bk0 + 8][bn], F + (size_t)(bk0 + 8) * NN + i0 + bn);
    cp16(&Bs[0][bk0][bn],     G + (size_t)bk0 * NN + j0 + bn);
    cp16(&Bs[0][bk0 + 8][bn], G + (size_t)(bk0 + 8) * NN + j0 + bn);
    CP_COMMIT();
    CP_WAIT0();
    __syncthreads();

    const int NS = CQ / 16;  // 4
    for (int s = 0; s < NS; s++) {
        const int buf = s & 1;
        if (s + 1 < NS) {
            const int kc = (s + 1) * 16;
            const int nb = buf ^ 1;
            cp16(&As[nb][bk0][bn],     F + (size_t)(kc + bk0) * NN + i0 + bn);
            cp16(&As[nb][bk0 + 8][bn], F + (size_t)(kc + bk0 + 8) * NN + i0 + bn);
            cp16(&Bs[nb][bk0][bn],     G + (size_t)(kc + bk0) * NN + j0 + bn);
            cp16(&Bs[nb][bk0 + 8][bn], G + (size_t)(kc + bk0 + 8) * NN + j0 + bn);
            CP_COMMIT();
        }
        compute_split_kA(As[buf], Bs[buf], c, gid, tig, mw, nw);
        CP_WAIT0();
        __syncthreads();
    }

    float* S = d_scores + (size_t)b * NN * NN;
    const float* mb = mask + (size_t)b * NN;

    float mrow[4][2];
#pragma unroll
    for (int f = 0; f < 4; f++) {
        const int r = i0 + mw + f * 16 + gid;
        mrow[f][0] = __ldg(&mb[r]);
        mrow[f][1] = __ldg(&mb[r + 8]);
    }

#pragma unroll
    for (int g = 0; g < 4; g++) {
        const int colL = nw + g * 8 + 2 * tig;
        float z0 = 0, z1 = 0, sm0 = 0, sm1 = 0;
#pragma unroll
        for (int f = 0; f < 4; f++) {
            const int r = i0 + mw + f * 16 + gid;
            float s0 = c[f][g].x, s1 = c[f][g].y, s2 = c[f][g].z, s3 = c[f][g].w;
            s0 = s0 >= 0.0f ? s0 : 0.2f * s0;
            s1 = s1 >= 0.0f ? s1 : 0.2f * s1;
            s2 = s2 >= 0.0f ? s2 : 0.2f * s2;
            s3 = s3 >= 0.0f ? s3 : 0.2f * s3;
            float e0 = __expf(fminf(s0, 75.0f));
            float e1 = __expf(fminf(s1, 75.0f));
            float e2 = __expf(fminf(s2, 75.0f));
            float e3 = __expf(fminf(s3, 75.0f));
            *(float2*)(S + (size_t)r * NN + j0 + colL) =
                make_float2(__uint_as_float(f2tf(e0)), __uint_as_float(f2tf(e1)));
            *(float2*)(S + (size_t)(r + 8) * NN + j0 + colL) =
                make_float2(__uint_as_float(f2tf(e2)), __uint_as_float(f2tf(e3)));
            z0 += e0 + e2;   z1 += e1 + e3;
            sm0 += mrow[f][0] * e0 + mrow[f][1] * e2;
            sm1 += mrow[f][0] * e1 + mrow[f][1] * e3;
        }
        atomicAdd(&sZ[colL], z0);       atomicAdd(&sZ[colL + 1], z1);
        atomicAdd(&sSm[colL], sm0);     atomicAdd(&sSm[colL + 1], sm1);
    }
    __syncthreads();
    if (tid < 128) {
        const size_t off = ((size_t)b * 8 + it) * NN + j0 + tid;
        d_partZ[off]  = sZ[tid];
        d_partSm[off] = sSm[tid];
    }
}

// ---------------------------------------------------------------------------
// K2b: fold 8 i-tile partials into column sums.
// ---------------------------------------------------------------------------
__global__ __launch_bounds__(256) void reduce_sums()
{
    const int b = blockIdx.y;
    const int j = blockIdx.x * 256 + threadIdx.x;
    float z = 0.0f, s = 0.0f;
#pragma unroll
    for (int t = 0; t < 8; t++) {
        const size_t off = ((size_t)b * 8 + t) * NN + j;
        z += d_partZ[off];
        s += d_partSm[off];
    }
    d_colZ[(size_t)b * NN + j]  = z;
    d_colSm[(size_t)b * NN + j] = s;
}

// ---------------------------------------------------------------------------
// K4: out[c][m] = gamma*(sum_n h'[c][n]*E[n][m])*mask[m]/(Sm+eps*Z) + x[c][m]
// Raw MMA, cp.async. (round-6 proven)
// ---------------------------------------------------------------------------
__global__ __launch_bounds__(256, 2) void out_gemm_t(
    const float* __restrict__ x,
    const float* __restrict__ mask,
    const float* __restrict__ gamma,
    float* __restrict__ out)
{
    __shared__ float As[2][128][20];
    __shared__ float Bs[2][16][136];

    const int b  = blockIdx.z;
    const int c0 = blockIdx.y * 128;
    const int m0 = blockIdx.x * 128;
    const float* h  = d_Y + (size_t)b * RTOT * NN + (size_t)(2 * CQ) * NN;
    const float* Bt = d_scores + (size_t)b * NN * NN;

    const int tid = threadIdx.x, lane = tid & 31, warp = tid >> 5;
    const int gid = lane >> 2, tig = lane & 3;
    const int mw = (warp >> 2) * 64, nw = (warp & 3) * 32;

    const int am0 = tid >> 2;
    const int ak  = (tid & 3) * 4;
    const float* arow0 = h + (size_t)(c0 + am0) * NN;
    const float* arow1 = h + (size_t)(c0 + am0 + 64) * NN;
    const int bk0 = tid >> 5;
    const int bn  = (tid & 31) * 4;

    float4 c[4][4];
#pragma unroll
    for (int f = 0; f < 4; f++)
#pragma unroll
        for (int g = 0; g < 4; g++) c[f][g] = make_float4(0, 0, 0, 0);

    cp16(&As[0][am0][ak],      arow0 + ak);
    cp16(&As[0][am0 + 64][ak], arow1 + ak);
    cp16(&Bs[0][bk0][bn],      Bt + (size_t)bk0 * NN + m0 + bn);
    cp16(&Bs[0][bk0 + 8][bn],  Bt + (size_t)(bk0 + 8) * NN + m0 + bn);
    CP_COMMIT();
    CP_WAIT0();
    __syncthreads();

    const int NS = NN / 16;  // 64
    for (int s = 0; s < NS; s++) {
        const int buf = s & 1;
        if (s + 1 < NS) {
            const int kc = (s + 1) * 16;
            const int nb = buf ^ 1;
            cp16(&As[nb][am0][ak],      arow0 + kc + ak);
            cp16(&As[nb][am0 + 64][ak], arow1 + kc + ak);
            cp16(&Bs[nb][bk0][bn],      Bt + (size_t)(kc + bk0) * NN + m0 + bn);
            cp16(&Bs[nb][bk0 + 8][bn],  Bt + (size_t)(kc + bk0 + 8) * NN + m0 + bn);
            CP_COMMIT();
        }
        compute_raw(As[buf], Bs[buf], c, gid, tig, mw, nw);
        CP_WAIT0();
        __syncthreads();
    }

    const float g0 = gamma[0];
    const float* xb = x + (size_t)b * CC * NN;
    float* ob = out + (size_t)b * CC * NN;
    const float* mb = mask + (size_t)b * NN;
    const float* zc = d_colZ + (size_t)b * NN;
    const float* sc = d_colSm + (size_t)b * NN;

#pragma unroll
    for (int g = 0; g < 4; g++) {
        const int col = m0 + nw + g * 8 + 2 * tig;
        float2 mv = *(const float2*)(mb + col);
        float2 zv = *(const float2*)(zc + col);
        float2 sv = *(const float2*)(sc + col);
        const float w0 = g0 * mv.x / (sv.x + 1e-6f * zv.x);
        const float w1 = g0 * mv.y / (sv.y + 1e-6f * zv.y);
#pragma unroll
        for (int f = 0; f < 4; f++) {
            const int r = c0 + mw + f * 16 + gid;
            float2 x0 = *(const float2*)(xb + (size_t)r * NN + col);
            float2 x1 = *(const float2*)(xb + (size_t)(r + 8) * NN + col);
            float2 o0, o1;
            o0.x = c[f][g].x * w0 + x0.x;
            o0.y = c[f][g].y * w1 + x0.y;
            o1.x = c[f][g].z * w0 + x1.x;
            o1.y = c[f][g].w * w1 + x1.y;
            *(float2*)(ob + (size_t)r * NN + col)       = o0;
            *(float2*)(ob + (size_t)(r + 8) * NN + col) = o1;
        }
    }
}

// ---------------------------------------------------------------------------
// Launch: fork the independent h'-chain onto a second stream so it overlaps
// the fg -> scores -> reduce chain; join before out_gemm.
// ---------------------------------------------------------------------------
extern "C" void kernel_launch(void* const* d_in, const int* in_sizes, int n_in,
                              void* d_out, int out_size)
{
    const float* x     = (const float*)d_in[0];
    const float* mask  = (const float*)d_in[1];
    const float* Wq    = (const float*)d_in[2];
    const float* Wk    = (const float*)d_in[3];
    const float* Wv    = (const float*)d_in[4];
    const float* gamma = (const float*)d_in[5];
    float* out = (float*)d_out;

    static cudaStream_t s2 = nullptr;
    static cudaEvent_t evFork = nullptr, evJoin = nullptr;
    if (s2 == nullptr) {
        cudaStreamCreateWithFlags(&s2, cudaStreamNonBlocking);
        cudaEventCreateWithFlags(&evFork, cudaEventDisableTiming);
        cudaEventCreateWithFlags(&evJoin, cudaEventDisableTiming);
    }

    // fork
    cudaEventRecord(evFork, 0);
    cudaStreamWaitEvent(s2, evFork, 0);

    // stream s2: h' chain
    round_x_kernel <<<(size_t)BB * CC * NN / (256 * 4), 256, 0, s2>>>(x);
    round_wv_kernel<<<(size_t)CC * CC / (256 * 4), 256, 0, s2>>>(Wv);
    qkv_h_gemm<<<dim3(NN / 128, CC / 128, BB), 256, 0, s2>>>(mask);
    cudaEventRecord(evJoin, s2);

    // stream 0: fg -> scores -> reduce
    qkv_fg_gemm<<<dim3(NN / 128, 1, BB), 256>>>(x, Wq, Wk);
    scores_gemm_t<<<dim3(NN / 128, NN / 128, BB), 256>>>(mask);
    reduce_sums<<<dim3(NN / 256, BB), 256>>>();

    // join, then the output GEMM
    cudaStreamWaitEvent(0, evJoin, 0);
    out_gemm_t<<<dim3(NN / 128, CC / 128, BB), 256>>>(x, mask, gamma, out);
}

// round 15
// speedup vs baseline: 1.8484x; 1.0278x over previous
#include <cuda_runtime.h>
#include <cstdint>

// Problem dims (fixed by the dataset)
#define BB   64
#define CC   512
#define NN   1024
#define CQ   64
#define RTOT 640

// Scratch
__device__ float d_Y[(size_t)BB * RTOT * NN];        // f/g rows 0..127 (plain), h' rows 128..639 (k-permuted)
__device__ float d_scores[(size_t)BB * NN * NN];     // E = exp(leaky(scores)), tf32-rounded
__device__ float d_xr[(size_t)BB * CC * NN];         // x rounded to tf32 (rna)
__device__ float d_Wvr[(size_t)CC * CC];             // Wv rounded to tf32, k-permuted
__device__ float d_partZ[(size_t)BB * 8 * NN];
__device__ float d_partSm[(size_t)BB * 8 * NN];
__device__ float d_colZ[(size_t)BB * NN];
__device__ float d_colSm[(size_t)BB * NN];

// ---------------------------------------------------------------------------
// helpers
// ---------------------------------------------------------------------------
__device__ __forceinline__ uint32_t f2tf(float f) {
    uint32_t u;
    asm("cvt.rna.tf32.f32 %0, %1;" : "=r"(u) : "f"(f));
    return u;
}

// k-permutation within 16-blocks: k = 16q + t + 4s  ->  pos = 16q + 4t + s
// so that {tig, tig+4, tig+8, tig+12} become contiguous at pos 4*tig.
__device__ __forceinline__ int kperm(int c) {
    return (c & ~15) | (((c & 3) << 2) | ((c & 15) >> 2));
}

__device__ __forceinline__ void mma8(float4& d, const uint32_t a[4], const uint32_t b[2]) {
    asm volatile(
        "mma.sync.aligned.m16n8k8.row.col.f32.tf32.tf32.f32 "
        "{%0,%1,%2,%3}, {%4,%5,%6,%7}, {%8,%9}, {%0,%1,%2,%3};"
        : "+f"(d.x), "+f"(d.y), "+f"(d.z), "+f"(d.w)
        : "r"(a[0]), "r"(a[1]), "r"(a[2]), "r"(a[3]), "r"(b[0]), "r"(b[1]));
}

__device__ __forceinline__ void cp16(void* dst_smem, const void* src_gmem) {
    uint32_t d = (uint32_t)__cvta_generic_to_shared(dst_smem);
    asm volatile("cp.async.cg.shared.global [%0], [%1], 16;" :: "r"(d), "l"(src_gmem));
}
#define CP_COMMIT() asm volatile("cp.async.commit_group;")
#define CP_WAIT0()  asm volatile("cp.async.wait_group 0;")

// ---------------------------------------------------------------------------
// Packed-A raw compute: A smem [128][16] (k-permuted quads -> LDS.128),
// B smem [16][136] (unchanged). One 128x128x16 chunk.
// Per chunk: 16 B LDS.32 + 8 A LDS.128 + 32 MMA.
// ---------------------------------------------------------------------------
__device__ __forceinline__ void compute_rawP(
    const float (*As)[16], const float (*Bs)[136],
    float4 (&c)[4][4], int gid, int tig, int mw, int nw)
{
    // all B fragments first
    uint32_t bfr[2][4][2];
#pragma unroll
    for (int ks2 = 0; ks2 < 2; ks2++)
#pragma unroll
        for (int g = 0; g < 4; g++) {
            const int n0 = nw + g * 8 + gid;
            bfr[ks2][g][0] = __float_as_uint(Bs[8 * ks2 + tig][n0]);
            bfr[ks2][g][1] = __float_as_uint(Bs[8 * ks2 + tig + 4][n0]);
        }
#pragma unroll
    for (int f = 0; f < 4; f++) {
        const int r = mw + f * 16 + gid;
        float4 qa0 = *(const float4*)&As[r][tig * 4];
        float4 qa1 = *(const float4*)&As[r + 8][tig * 4];
        uint32_t a0[4] = { __float_as_uint(qa0.x), __float_as_uint(qa1.x),
                           __float_as_uint(qa0.y), __float_as_uint(qa1.y) };
        uint32_t a8[4] = { __float_as_uint(qa0.z), __float_as_uint(qa1.z),
                           __float_as_uint(qa0.w), __float_as_uint(qa1.w) };
#pragma unroll
        for (int g = 0; g < 4; g++) {
            mma8(c[f][g], a0, bfr[0][g]);
            mma8(c[f][g], a8, bfr[1][g]);
        }
    }
}

// ---------------------------------------------------------------------------
// Split (3xTF32) computes — unchanged, round-6/13 proven.
// ---------------------------------------------------------------------------
__device__ __forceinline__ void compute_split_mA(
    const float (*As)[20], const float (*Bs)[136],
    float4 (&c)[4][4], int gid, int tig, int mw, int nw)
{
#pragma unroll
    for (int ks = 0; ks < 16; ks += 8) {
        uint32_t ahi[4][4], alo[4][4];
        uint32_t bhi[4][2], blo[4][2];
#pragma unroll
        for (int f = 0; f < 4; f++) {
            const int r = mw + f * 16 + gid;
            float a0 = As[r][ks + tig];
            float a1 = As[r + 8][ks + tig];
            float a2 = As[r][ks + tig + 4];
            float a3 = As[r + 8][ks + tig + 4];
            ahi[f][0] = f2tf(a0); ahi[f][1] = f2tf(a1);
            ahi[f][2] = f2tf(a2); ahi[f][3] = f2tf(a3);
            alo[f][0] = f2tf(a0 - __uint_as_float(ahi[f][0]));
            alo[f][1] = f2tf(a1 - __uint_as_float(ahi[f][1]));
            alo[f][2] = f2tf(a2 - __uint_as_float(ahi[f][2]));
            alo[f][3] = f2tf(a3 - __uint_as_float(ahi[f][3]));
        }
#pragma unroll
        for (int g = 0; g < 4; g++) {
            const int n0 = nw + g * 8 + gid;
            float b0 = Bs[ks + tig][n0];
            float b1 = Bs[ks + tig + 4][n0];
            bhi[g][0] = f2tf(b0); bhi[g][1] = f2tf(b1);
            blo[g][0] = f2tf(b0 - __uint_as_float(bhi[g][0]));
            blo[g][1] = f2tf(b1 - __uint_as_float(bhi[g][1]));
        }
#pragma unroll
        for (int f = 0; f < 4; f++)
#pragma unroll
            for (int g = 0; g < 4; g++) {
                mma8(c[f][g], ahi[f], blo[g]);
                mma8(c[f][g], alo[f], bhi[g]);
                mma8(c[f][g], ahi[f], bhi[g]);
            }
    }
}

__device__ __forceinline__ void compute_split_kA(
    const float (*As)[136], const float (*Bs)[136],
    float4 (&c)[4][4], int gid, int tig, int mw, int nw)
{
#pragma unroll
    for (int ks = 0; ks < 16; ks += 8) {
        uint32_t ahi[4][4], alo[4][4];
        uint32_t bhi[4][2], blo[4][2];
#pragma unroll
        for (int f = 0; f < 4; f++) {
            const int r = mw + f * 16 + gid;
            float a0 = As[ks + tig][r];
            float a1 = As[ks + tig][r + 8];
            float a2 = As[ks + tig + 4][r];
            float a3 = As[ks + tig + 4][r + 8];
            ahi[f][0] = f2tf(a0); ahi[f][1] = f2tf(a1);
            ahi[f][2] = f2tf(a2); ahi[f][3] = f2tf(a3);
            alo[f][0] = f2tf(a0 - __uint_as_float(ahi[f][0]));
            alo[f][1] = f2tf(a1 - __uint_as_float(ahi[f][1]));
            alo[f][2] = f2tf(a2 - __uint_as_float(ahi[f][2]));
            alo[f][3] = f2tf(a3 - __uint_as_float(ahi[f][3]));
        }
#pragma unroll
        for (int g = 0; g < 4; g++) {
            const int n0 = nw + g * 8 + gid;
            float b0 = Bs[ks + tig][n0];
            float b1 = Bs[ks + tig + 4][n0];
            bhi[g][0] = f2tf(b0); bhi[g][1] = f2tf(b1);
            blo[g][0] = f2tf(b0 - __uint_as_float(bhi[g][0]));
            blo[g][1] = f2tf(b1 - __uint_as_float(bhi[g][1]));
        }
#pragma unroll
        for (int f = 0; f < 4; f++)
#pragma unroll
            for (int g = 0; g < 4; g++) {
                mma8(c[f][g], ahi[f], blo[g]);
                mma8(c[f][g], alo[f], bhi[g]);
                mma8(c[f][g], ahi[f], bhi[g]);
            }
    }
}

// ---------------------------------------------------------------------------
// K0: round x (plain) and Wv (k-permuted) to tf32 once.
// ---------------------------------------------------------------------------
__global__ __launch_bounds__(256) void round_x_kernel(const float* __restrict__ x)
{
    const size_t i = ((size_t)blockIdx.x * 256 + threadIdx.x) * 4;
    float4 v = *(const float4*)(x + i);
    v.x = __uint_as_float(f2tf(v.x));
    v.y = __uint_as_float(f2tf(v.y));
    v.z = __uint_as_float(f2tf(v.z));
    v.w = __uint_as_float(f2tf(v.w));
    *(float4*)(d_xr + i) = v;
}

__global__ __launch_bounds__(256) void round_wv_kernel(const float* __restrict__ Wv)
{
    const size_t i = ((size_t)blockIdx.x * 256 + threadIdx.x) * 4;
    const size_t row = i / CC;
    const int cb = (int)(i % CC);           // multiple of 4
    float4 v = *(const float4*)(Wv + i);
    float vr[4];
    vr[0] = __uint_as_float(f2tf(v.x));
    vr[1] = __uint_as_float(f2tf(v.y));
    vr[2] = __uint_as_float(f2tf(v.z));
    vr[3] = __uint_as_float(f2tf(v.w));
    float* drow = d_Wvr + row * CC;
#pragma unroll
    for (int j = 0; j < 4; j++)
        drow[kperm(cb + j)] = vr[j];
}

// ---------------------------------------------------------------------------
// K1a: f,g projection = [Wq;Wk] @ x.  SPLIT tf32, cp.async. (proven)
// ---------------------------------------------------------------------------
__global__ __launch_bounds__(256, 2) void qkv_fg_gemm(
    const float* __restrict__ x,
    const float* __restrict__ Wq,
    const float* __restrict__ Wk)
{
    __shared__ float As[2][128][20];
    __shared__ float Bs[2][16][136];

    const int b = blockIdx.z;
    const int col0 = blockIdx.x * 128;
    const float* xb = x + (size_t)b * CC * NN;

    const int tid = threadIdx.x, lane = tid & 31, warp = tid >> 5;
    const int gid = lane >> 2, tig = lane & 3;
    const int mw = (warp >> 2) * 64, nw = (warp & 3) * 32;

    const int am0 = tid >> 2;
    const int ak  = (tid & 3) * 4;
    const float* arow0 = Wq + (size_t)am0 * CC;
    const float* arow1 = Wk + (size_t)am0 * CC;
    const int bk0 = tid >> 5;
    const int bn  = (tid & 31) * 4;

    float4 c[4][4];
#pragma unroll
    for (int f = 0; f < 4; f++)
#pragma unroll
        for (int g = 0; g < 4; g++) c[f][g] = make_float4(0, 0, 0, 0);

    cp16(&As[0][am0][ak],       arow0 + ak);
    cp16(&As[0][am0 + 64][ak],  arow1 + ak);
    cp16(&Bs[0][bk0][bn],       xb + (size_t)bk0 * NN + col0 + bn);
    cp16(&Bs[0][bk0 + 8][bn],   xb + (size_t)(bk0 + 8) * NN + col0 + bn);
    CP_COMMIT();
    CP_WAIT0();
    __syncthreads();

    const int NS = CC / 16;
    for (int s = 0; s < NS; s++) {
        const int buf = s & 1;
        if (s + 1 < NS) {
            const int kc = (s + 1) * 16;
            const int nb = buf ^ 1;
            cp16(&As[nb][am0][ak],      arow0 + kc + ak);
            cp16(&As[nb][am0 + 64][ak], arow1 + kc + ak);
            cp16(&Bs[nb][bk0][bn],      xb + (size_t)(kc + bk0) * NN + col0 + bn);
            cp16(&Bs[nb][bk0 + 8][bn],  xb + (size_t)(kc + bk0 + 8) * NN + col0 + bn);
            CP_COMMIT();
        }
        compute_split_mA(As[buf], Bs[buf], c, gid, tig, mw, nw);
        CP_WAIT0();
        __syncthreads();
    }

    float* yb = d_Y + (size_t)b * RTOT * NN;
#pragma unroll
    for (int f = 0; f < 4; f++) {
        const int r = mw + f * 16 + gid;
#pragma unroll
        for (int g = 0; g < 4; g++) {
            const int col = col0 + nw + g * 8 + 2 * tig;
            *(float2*)(yb + (size_t)r * NN + col)       = make_float2(c[f][g].x, c[f][g].y);
            *(float2*)(yb + (size_t)(r + 8) * NN + col) = make_float2(c[f][g].z, c[f][g].w);
        }
    }
}

// ---------------------------------------------------------------------------
// K1b: h' = (Wvr_perm @ xr) * mask[col], tf32-rounded; h' stored K-PERMUTED.
// A packed ([128][16] + LDS.128), B unchanged.
// ---------------------------------------------------------------------------
__global__ __launch_bounds__(256, 2) void qkv_h_gemm(const float* __restrict__ mask)
{
    __shared__ float As[2][128][16];
    __shared__ float Bs[2][16][136];

    const int b = blockIdx.z;
    const int row0 = blockIdx.y * 128;
    const int col0 = blockIdx.x * 128;
    const float* xb = d_xr + (size_t)b * CC * NN;

    const int tid = threadIdx.x, lane = tid & 31, warp = tid >> 5;
    const int gid = lane >> 2, tig = lane & 3;
    const int mw = (warp >> 2) * 64, nw = (warp & 3) * 32;

    const int am0 = tid >> 2;
    const int ak  = (tid & 3) * 4;
    const float* arow0 = d_Wvr + (size_t)(row0 + am0) * CC;
    const float* arow1 = d_Wvr + (size_t)(row0 + am0 + 64) * CC;
    const int bk0 = tid >> 5;
    const int bn  = (tid & 31) * 4;

    float4 c[4][4];
#pragma unroll
    for (int f = 0; f < 4; f++)
#pragma unroll
        for (int g = 0; g < 4; g++) c[f][g] = make_float4(0, 0, 0, 0);

    cp16(&As[0][am0][ak],      arow0 + ak);
    cp16(&As[0][am0 + 64][ak], arow1 + ak);
    cp16(&Bs[0][bk0][bn],      xb + (size_t)bk0 * NN + col0 + bn);
    cp16(&Bs[0][bk0 + 8][bn],  xb + (size_t)(bk0 + 8) * NN + col0 + bn);
    CP_COMMIT();
    CP_WAIT0();
    __syncthreads();

    const int NS = CC / 16;
    for (int s = 0; s < NS; s++) {
        const int buf = s & 1;
        if (s + 1 < NS) {
            const int kc = (s + 1) * 16;
            const int nb = buf ^ 1;
            cp16(&As[nb][am0][ak],      arow0 + kc + ak);
            cp16(&As[nb][am0 + 64][ak], arow1 + kc + ak);
            cp16(&Bs[nb][bk0][bn],      xb + (size_t)(kc + bk0) * NN + col0 + bn);
            cp16(&Bs[nb][bk0 + 8][bn],  xb + (size_t)(kc + bk0 + 8) * NN + col0 + bn);
            CP_COMMIT();
        }
        compute_rawP(As[buf], Bs[buf], c, gid, tig, mw, nw);
        CP_WAIT0();
        __syncthreads();
    }

    float* yb = d_Y + (size_t)b * RTOT * NN + (size_t)(2 * CQ + row0) * NN;
    const float* mb = mask + (size_t)b * NN;
#pragma unroll
    for (int f = 0; f < 4; f++) {
        const int r = mw + f * 16 + gid;
#pragma unroll
        for (int g = 0; g < 4; g++) {
            const int col = col0 + nw + g * 8 + 2 * tig;
            float2 mv = *(const float2*)(mb + col);
            const int pc = kperm(col);      // kperm(col+1) == pc + 4 (col even)
            float v0 = __uint_as_float(f2tf(c[f][g].x * mv.x));
            float v1 = __uint_as_float(f2tf(c[f][g].y * mv.y));
            float v2 = __uint_as_float(f2tf(c[f][g].z * mv.x));
            float v3 = __uint_as_float(f2tf(c[f][g].w * mv.y));
            yb[(size_t)r * NN + pc]           = v0;
            yb[(size_t)r * NN + pc + 4]       = v1;
            yb[(size_t)(r + 8) * NN + pc]     = v2;
            yb[(size_t)(r + 8) * NN + pc + 4] = v3;
        }
    }
}

// ---------------------------------------------------------------------------
// K2: E = tf32_round(exp(leaky(F^T G))), K=64, SPLIT tf32. (proven, unchanged)
// ---------------------------------------------------------------------------
__global__ __launch_bounds__(256, 2) void scores_gemm_t(const float* __restrict__ mask)
{
    __shared__ float As[2][16][136];
    __shared__ float Bs[2][16][136];
    __shared__ float sZ[128];
    __shared__ float sSm[128];

    const int b  = blockIdx.z;
    const int it = blockIdx.y;
    const int i0 = it * 128;
    const int j0 = blockIdx.x * 128;
    const float* F = d_Y + (size_t)b * RTOT * NN;
    const float* G = F + (size_t)CQ * NN;

    const int tid = threadIdx.x, lane = tid & 31, warp = tid >> 5;
    const int gid = lane >> 2, tig = lane & 3;
    const int mw = (warp >> 2) * 64, nw = (warp & 3) * 32;
    const int bk0 = tid >> 5;
    const int bn  = (tid & 31) * 4;

    if (tid < 128) { sZ[tid] = 0.0f; sSm[tid] = 0.0f; }

    float4 c[4][4];
#pragma unroll
    for (int f = 0; f < 4; f++)
#pragma unroll
        for (int g = 0; g < 4; g++) c[f][g] = make_float4(0, 0, 0, 0);

    cp16(&As[0][bk0][bn],     F + (size_t)bk0 * NN + i0 + bn);
    cp16(&As[0][bk0 + 8][bn], F + (size_t)(bk0 + 8) * NN + i0 + bn);
    cp16(&Bs[0][bk0][bn],     G + (size_t)bk0 * NN + j0 + bn);
    cp16(&Bs[0][bk0 + 8][bn], G + (size_t)(bk0 + 8) * NN + j0 + bn);
    CP_COMMIT();
    CP_WAIT0();
    __syncthreads();

    const int NS = CQ / 16;  // 4
    for (int s = 0; s < NS; s++) {
        const int buf = s & 1;
        if (s + 1 < NS) {
            const int kc = (s + 1) * 16;
            const int nb = buf ^ 1;
            cp16(&As[nb][bk0][bn],     F + (size_t)(kc + bk0) * NN + i0 + bn);
            cp16(&As[nb][bk0 + 8][bn], F + (size_t)(kc + bk0 + 8) * NN + i0 + bn);
            cp16(&Bs[nb][bk0][bn],     G + (size_t)(kc + bk0) * NN + j0 + bn);
            cp16(&Bs[nb][bk0 + 8][bn], G + (size_t)(kc + bk0 + 8) * NN + j0 + bn);
            CP_COMMIT();
        }
        compute_split_kA(As[buf], Bs[buf], c, gid, tig, mw, nw);
        CP_WAIT0();
        __syncthreads();
    }

    float* S = d_scores + (size_t)b * NN * NN;
    const float* mb = mask + (size_t)b * NN;

    float mrow[4][2];
#pragma unroll
    for (int f = 0; f < 4; f++) {
        const int r = i0 + mw + f * 16 + gid;
        mrow[f][0] = __ldg(&mb[r]);
        mrow[f][1] = __ldg(&mb[r + 8]);
    }

#pragma unroll
    for (int g = 0; g < 4; g++) {
        const int colL = nw + g * 8 + 2 * tig;
        float z0 = 0, z1 = 0, sm0 = 0, sm1 = 0;
#pragma unroll
        for (int f = 0; f < 4; f++) {
            const int r = i0 + mw + f * 16 + gid;
            float s0 = c[f][g].x, s1 = c[f][g].y, s2 = c[f][g].z, s3 = c[f][g].w;
            s0 = s0 >= 0.0f ? s0 : 0.2f * s0;
            s1 = s1 >= 0.0f ? s1 : 0.2f * s1;
            s2 = s2 >= 0.0f ? s2 : 0.2f * s2;
            s3 = s3 >= 0.0f ? s3 : 0.2f * s3;
            float e0 = __expf(fminf(s0, 75.0f));
            float e1 = __expf(fminf(s1, 75.0f));
            float e2 = __expf(fminf(s2, 75.0f));
            float e3 = __expf(fminf(s3, 75.0f));
            *(float2*)(S + (size_t)r * NN + j0 + colL) =
                make_float2(__uint_as_float(f2tf(e0)), __uint_as_float(f2tf(e1)));
            *(float2*)(S + (size_t)(r + 8) * NN + j0 + colL) =
                make_float2(__uint_as_float(f2tf(e2)), __uint_as_float(f2tf(e3)));
            z0 += e0 + e2;   z1 += e1 + e3;
            sm0 += mrow[f][0] * e0 + mrow[f][1] * e2;
            sm1 += mrow[f][0] * e1 + mrow[f][1] * e3;
        }
        atomicAdd(&sZ[colL], z0);       atomicAdd(&sZ[colL + 1], z1);
        atomicAdd(&sSm[colL], sm0);     atomicAdd(&sSm[colL + 1], sm1);
    }
    __syncthreads();
    if (tid < 128) {
        const size_t off = ((size_t)b * 8 + it) * NN + j0 + tid;
        d_partZ[off]  = sZ[tid];
        d_partSm[off] = sSm[tid];
    }
}

// ---------------------------------------------------------------------------
// K2b: fold 8 i-tile partials into column sums.
// ---------------------------------------------------------------------------
__global__ __launch_bounds__(256) void reduce_sums()
{
    const int b = blockIdx.y;
    const int j = blockIdx.x * 256 + threadIdx.x;
    float z = 0.0f, s = 0.0f;
#pragma unroll
    for (int t = 0; t < 8; t++) {
        const size_t off = ((size_t)b * 8 + t) * NN + j;
        z += d_partZ[off];
        s += d_partSm[off];
    }
    d_colZ[(size_t)b * NN + j]  = z;
    d_colSm[(size_t)b * NN + j] = s;
}

// ---------------------------------------------------------------------------
// K4: out[c][m] = gamma*(sum_n h'[c][n]*E[n][m])*mask[m]/(Sm+eps*Z) + x[c][m]
// A = h' (k-permuted in gmem) -> packed [128][16] + LDS.128. B = E unchanged.
// ---------------------------------------------------------------------------
__global__ __launch_bounds__(256, 2) void out_gemm_t(
    const float* __restrict__ x,
    const float* __restrict__ mask,
    const float* __restrict__ gamma,
    float* __restrict__ out)
{
    __shared__ float As[2][128][16];
    __shared__ float Bs[2][16][136];

    const int b  = blockIdx.z;
    const int c0 = blockIdx.y * 128;
    const int m0 = blockIdx.x * 128;
    const float* h  = d_Y + (size_t)b * RTOT * NN + (size_t)(2 * CQ) * NN;
    const float* Bt = d_scores + (size_t)b * NN * NN;

    const int tid = threadIdx.x, lane = tid & 31, warp = tid >> 5;
    const int gid = lane >> 2, tig = lane & 3;
    const int mw = (warp >> 2) * 64, nw = (warp & 3) * 32;

    const int am0 = tid >> 2;
    const int ak  = (tid & 3) * 4;
    const float* arow0 = h + (size_t)(c0 + am0) * NN;
    const float* arow1 = h + (size_t)(c0 + am0 + 64) * NN;
    const int bk0 = tid >> 5;
    const int bn  = (tid & 31) * 4;

    float4 c[4][4];
#pragma unroll
    for (int f = 0; f < 4; f++)
#pragma unroll
        for (int g = 0; g < 4; g++) c[f][g] = make_float4(0, 0, 0, 0);

    cp16(&As[0][am0][ak],      arow0 + ak);
    cp16(&As[0][am0 + 64][ak], arow1 + ak);
    cp16(&Bs[0][bk0][bn],      Bt + (size_t)bk0 * NN + m0 + bn);
    cp16(&Bs[0][bk0 + 8][bn],  Bt + (size_t)(bk0 + 8) * NN + m0 + bn);
    CP_COMMIT();
    CP_WAIT0();
    __syncthreads();

    const int NS = NN / 16;  // 64
    for (int s = 0; s < NS; s++) {
        const int buf = s & 1;
        if (s + 1 < NS) {
            const int kc = (s + 1) * 16;
            const int nb = buf ^ 1;
            cp16(&As[nb][am0][ak],      arow0 + kc + ak);
            cp16(&As[nb][am0 + 64][ak], arow1 + kc + ak);
            cp16(&Bs[nb][bk0][bn],      Bt + (size_t)(kc + bk0) * NN + m0 + bn);
            cp16(&Bs[nb][bk0 + 8][bn],  Bt + (size_t)(kc + bk0 + 8) * NN + m0 + bn);
            CP_COMMIT();
        }
        compute_rawP(As[buf], Bs[buf], c, gid, tig, mw, nw);
        CP_WAIT0();
        __syncthreads();
    }

    const float g0 = gamma[0];
    const float* xb = x + (size_t)b * CC * NN;
    float* ob = out + (size_t)b * CC * NN;
    const float* mb = mask + (size_t)b * NN;
    const float* zc = d_colZ + (size_t)b * NN;
    const float* sc = d_colSm + (size_t)b * NN;

#pragma unroll
    for (int g = 0; g < 4; g++) {
        const int col = m0 + nw + g * 8 + 2 * tig;
        float2 mv = *(const float2*)(mb + col);
        float2 zv = *(const float2*)(zc + col);
        float2 sv = *(const float2*)(sc + col);
        const float w0 = g0 * mv.x / (sv.x + 1e-6f * zv.x);
        const float w1 = g0 * mv.y / (sv.y + 1e-6f * zv.y);
#pragma unroll
        for (int f = 0; f < 4; f++) {
            const int r = c0 + mw + f * 16 + gid;
            float2 x0 = *(const float2*)(xb + (size_t)r * NN + col);
            float2 x1 = *(const float2*)(xb + (size_t)(r + 8) * NN + col);
            float2 o0, o1;
            o0.x = c[f][g].x * w0 + x0.x;
            o0.y = c[f][g].y * w1 + x0.y;
            o1.x = c[f][g].z * w0 + x1.x;
            o1.y = c[f][g].w * w1 + x1.y;
            *(float2*)(ob + (size_t)r * NN + col)       = o0;
            *(float2*)(ob + (size_t)(r + 8) * NN + col) = o1;
        }
    }
}

// ---------------------------------------------------------------------------
// Launch: fork the h'-chain onto a second stream (overlaps fg -> scores ->
// reduce); join before out_gemm.
// ---------------------------------------------------------------------------
extern "C" void kernel_launch(void* const* d_in, const int* in_sizes, int n_in,
                              void* d_out, int out_size)
{
    const float* x     = (const float*)d_in[0];
    const float* mask  = (const float*)d_in[1];
    const float* Wq    = (const float*)d_in[2];
    const float* Wk    = (const float*)d_in[3];
    const float* Wv    = (const float*)d_in[4];
    const float* gamma = (const float*)d_in[5];
    float* out = (float*)d_out;

    static cudaStream_t s2 = nullptr;
    static cudaEvent_t evFork = nullptr, evJoin = nullptr;
    if (s2 == nullptr) {
        cudaStreamCreateWithFlags(&s2, cudaStreamNonBlocking);
        cudaEventCreateWithFlags(&evFork, cudaEventDisableTiming);
        cudaEventCreateWithFlags(&evJoin, cudaEventDisableTiming);
    }

    // fork
    cudaEventRecord(evFork, 0);
    cudaStreamWaitEvent(s2, evFork, 0);

    // stream s2: h' chain
    round_x_kernel <<<(size_t)BB * CC * NN / (256 * 4), 256, 0, s2>>>(x);
    round_wv_kernel<<<(size_t)CC * CC / (256 * 4), 256, 0, s2>>>(Wv);
    qkv_h_gemm<<<dim3(NN / 128, CC / 128, BB), 256, 0, s2>>>(mask);
    cudaEventRecord(evJoin, s2);

    // stream 0: fg -> scores -> reduce
    qkv_fg_gemm<<<dim3(NN / 128, 1, BB), 256>>>(x, Wq, Wk);
    scores_gemm_t<<<dim3(NN / 128, NN / 128, BB), 256>>>(mask);
    reduce_sums<<<dim3(NN / 256, BB), 256>>>();

    // join, then the output GEMM
    cudaStreamWaitEvent(0, evJoin, 0);
    out_gemm_t<<<dim3(NN / 128, CC / 128, BB), 256>>>(x, mask, gamma, out);
}

// round 16
// speedup vs baseline: 2.2890x; 1.2383x over previous
#include <cuda_runtime.h>
#include <cuda_bf16.h>
#include <cstdint>

// Problem dims (fixed by the dataset)
#define BB   64
#define CC   512
#define NN   1024
#define CQ   64

// Scratch
__device__ float d_Y[(size_t)BB * 128 * NN];            // f rows 0..63, g rows 64..127
__device__ float d_xr[(size_t)BB * CC * NN];            // x rounded to tf32 (rna)
__device__ float d_Wvr[(size_t)CC * CC];                // Wv tf32, fp32-kperm
__device__ __nv_bfloat16 d_Hb[(size_t)BB * CC * NN];    // h' bf16, pair-perm cols
__device__ __nv_bfloat16 d_T[(size_t)BB * NN * NN];     // T[j][i] = E[i][j], bf16 pair-perm
__device__ float d_partZ[(size_t)BB * 8 * NN];
__device__ float d_partSm[(size_t)BB * 8 * NN];
__device__ float d_colZ[(size_t)BB * NN];
__device__ float d_colSm[(size_t)BB * NN];

// ---------------------------------------------------------------------------
// helpers
// ---------------------------------------------------------------------------
__device__ __forceinline__ uint32_t f2tf(float f) {
    uint32_t u;
    asm("cvt.rna.tf32.f32 %0, %1;" : "=r"(u) : "f"(f));
    return u;
}

// fp32 k-permutation within 16-blocks (round-14 proven, for Wvr LDS.128):
__device__ __forceinline__ int kperm(int c) {
    return (c & ~15) | (((c & 3) << 2) | ((c & 15) >> 2));
}

__device__ __forceinline__ void mma8(float4& d, const uint32_t a[4], const uint32_t b[2]) {
    asm volatile(
        "mma.sync.aligned.m16n8k8.row.col.f32.tf32.tf32.f32 "
        "{%0,%1,%2,%3}, {%4,%5,%6,%7}, {%8,%9}, {%0,%1,%2,%3};"
        : "+f"(d.x), "+f"(d.y), "+f"(d.z), "+f"(d.w)
        : "r"(a[0]), "r"(a[1]), "r"(a[2]), "r"(a[3]), "r"(b[0]), "r"(b[1]));
}

__device__ __forceinline__ void mma16(float4& d, const uint32_t a[4], const uint32_t b[2]) {
    asm volatile(
        "mma.sync.aligned.m16n8k16.row.col.f32.bf16.bf16.f32 "
        "{%0,%1,%2,%3}, {%4,%5,%6,%7}, {%8,%9}, {%0,%1,%2,%3};"
        : "+f"(d.x), "+f"(d.y), "+f"(d.z), "+f"(d.w)
        : "r"(a[0]), "r"(a[1]), "r"(a[2]), "r"(a[3]), "r"(b[0]), "r"(b[1]));
}

__device__ __forceinline__ void cp16(void* dst_smem, const void* src_gmem) {
    uint32_t d = (uint32_t)__cvta_generic_to_shared(dst_smem);
    asm volatile("cp.async.cg.shared.global [%0], [%1], 16;" :: "r"(d), "l"(src_gmem));
}
#define CP_COMMIT() asm volatile("cp.async.commit_group;")
#define CP_WAIT0()  asm volatile("cp.async.wait_group 0;")

// ---------------------------------------------------------------------------
// fp32 packed-A raw tf32 compute (round-15 proven): A [128][16] fp32 kperm,
// B [16][136].
// ---------------------------------------------------------------------------
__device__ __forceinline__ void compute_rawP(
    const float (*As)[16], const float (*Bs)[136],
    float4 (&c)[4][4], int gid, int tig, int mw, int nw)
{
    uint32_t bfr[2][4][2];
#pragma unroll
    for (int ks2 = 0; ks2 < 2; ks2++)
#pragma unroll
        for (int g = 0; g < 4; g++) {
            const int n0 = nw + g * 8 + gid;
            bfr[ks2][g][0] = __float_as_uint(Bs[8 * ks2 + tig][n0]);
            bfr[ks2][g][1] = __float_as_uint(Bs[8 * ks2 + tig + 4][n0]);
        }
#pragma unroll
    for (int f = 0; f < 4; f++) {
        const int r = mw + f * 16 + gid;
        float4 qa0 = *(const float4*)&As[r][tig * 4];
        float4 qa1 = *(const float4*)&As[r + 8][tig * 4];
        uint32_t a0[4] = { __float_as_uint(qa0.x), __float_as_uint(qa1.x),
                           __float_as_uint(qa0.y), __float_as_uint(qa1.y) };
        uint32_t a8[4] = { __float_as_uint(qa0.z), __float_as_uint(qa1.z),
                           __float_as_uint(qa0.w), __float_as_uint(qa1.w) };
#pragma unroll
        for (int g = 0; g < 4; g++) {
            mma8(c[f][g], a0, bfr[0][g]);
            mma8(c[f][g], a8, bfr[1][g]);
        }
    }
}

// ---------------------------------------------------------------------------
// Split (3xTF32) computes — proven, unchanged.
// ---------------------------------------------------------------------------
__device__ __forceinline__ void compute_split_mA(
    const float (*As)[20], const float (*Bs)[136],
    float4 (&c)[4][4], int gid, int tig, int mw, int nw)
{
#pragma unroll
    for (int ks = 0; ks < 16; ks += 8) {
        uint32_t ahi[4][4], alo[4][4];
        uint32_t bhi[4][2], blo[4][2];
#pragma unroll
        for (int f = 0; f < 4; f++) {
            const int r = mw + f * 16 + gid;
            float a0 = As[r][ks + tig];
            float a1 = As[r + 8][ks + tig];
            float a2 = As[r][ks + tig + 4];
            float a3 = As[r + 8][ks + tig + 4];
            ahi[f][0] = f2tf(a0); ahi[f][1] = f2tf(a1);
            ahi[f][2] = f2tf(a2); ahi[f][3] = f2tf(a3);
            alo[f][0] = f2tf(a0 - __uint_as_float(ahi[f][0]));
            alo[f][1] = f2tf(a1 - __uint_as_float(ahi[f][1]));
            alo[f][2] = f2tf(a2 - __uint_as_float(ahi[f][2]));
            alo[f][3] = f2tf(a3 - __uint_as_float(ahi[f][3]));
        }
#pragma unroll
        for (int g = 0; g < 4; g++) {
            const int n0 = nw + g * 8 + gid;
            float b0 = Bs[ks + tig][n0];
            float b1 = Bs[ks + tig + 4][n0];
            bhi[g][0] = f2tf(b0); bhi[g][1] = f2tf(b1);
            blo[g][0] = f2tf(b0 - __uint_as_float(bhi[g][0]));
            blo[g][1] = f2tf(b1 - __uint_as_float(bhi[g][1]));
        }
#pragma unroll
        for (int f = 0; f < 4; f++)
#pragma unroll
            for (int g = 0; g < 4; g++) {
                mma8(c[f][g], ahi[f], blo[g]);
                mma8(c[f][g], alo[f], bhi[g]);
                mma8(c[f][g], ahi[f], bhi[g]);
            }
    }
}

__device__ __forceinline__ void compute_split_kA(
    const float (*As)[136], const float (*Bs)[136],
    float4 (&c)[4][4], int gid, int tig, int mw, int nw)
{
#pragma unroll
    for (int ks = 0; ks < 16; ks += 8) {
        uint32_t ahi[4][4], alo[4][4];
        uint32_t bhi[4][2], blo[4][2];
#pragma unroll
        for (int f = 0; f < 4; f++) {
            const int r = mw + f * 16 + gid;
            float a0 = As[ks + tig][r];
            float a1 = As[ks + tig][r + 8];
            float a2 = As[ks + tig + 4][r];
            float a3 = As[ks + tig + 4][r + 8];
            ahi[f][0] = f2tf(a0); ahi[f][1] = f2tf(a1);
            ahi[f][2] = f2tf(a2); ahi[f][3] = f2tf(a3);
            alo[f][0] = f2tf(a0 - __uint_as_float(ahi[f][0]));
            alo[f][1] = f2tf(a1 - __uint_as_float(ahi[f][1]));
            alo[f][2] = f2tf(a2 - __uint_as_float(ahi[f][2]));
            alo[f][3] = f2tf(a3 - __uint_as_float(ahi[f][3]));
        }
#pragma unroll
        for (int g = 0; g < 4; g++) {
            const int n0 = nw + g * 8 + gid;
            float b0 = Bs[ks + tig][n0];
            float b1 = Bs[ks + tig + 4][n0];
            bhi[g][0] = f2tf(b0); bhi[g][1] = f2tf(b1);
            blo[g][0] = f2tf(b0 - __uint_as_float(bhi[g][0]));
            blo[g][1] = f2tf(b1 - __uint_as_float(bhi[g][1]));
        }
#pragma unroll
        for (int f = 0; f < 4; f++)
#pragma unroll
            for (int g = 0; g < 4; g++) {
                mma8(c[f][g], ahi[f], blo[g]);
                mma8(c[f][g], alo[f], bhi[g]);
                mma8(c[f][g], ahi[f], bhi[g]);
            }
    }
}

// ---------------------------------------------------------------------------
// K0: round x (plain) and Wv (fp32-kperm) to tf32 once.
// ---------------------------------------------------------------------------
__global__ __launch_bounds__(256) void round_x_kernel(const float* __restrict__ x)
{
    const size_t i = ((size_t)blockIdx.x * 256 + threadIdx.x) * 4;
    float4 v = *(const float4*)(x + i);
    v.x = __uint_as_float(f2tf(v.x));
    v.y = __uint_as_float(f2tf(v.y));
    v.z = __uint_as_float(f2tf(v.z));
    v.w = __uint_as_float(f2tf(v.w));
    *(float4*)(d_xr + i) = v;
}

__global__ __launch_bounds__(256) void round_wv_kernel(const float* __restrict__ Wv)
{
    const size_t i = ((size_t)blockIdx.x * 256 + threadIdx.x) * 4;
    const size_t row = i / CC;
    const int cb = (int)(i % CC);
    float4 v = *(const float4*)(Wv + i);
    float vr[4];
    vr[0] = __uint_as_float(f2tf(v.x));
    vr[1] = __uint_as_float(f2tf(v.y));
    vr[2] = __uint_as_float(f2tf(v.z));
    vr[3] = __uint_as_float(f2tf(v.w));
    float* drow = d_Wvr + row * CC;
#pragma unroll
    for (int j = 0; j < 4; j++)
        drow[kperm(cb + j)] = vr[j];
}

// ---------------------------------------------------------------------------
// K1a: f,g projection = [Wq;Wk] @ x.  SPLIT tf32, cp.async. (proven)
// ---------------------------------------------------------------------------
__global__ __launch_bounds__(256, 2) void qkv_fg_gemm(
    const float* __restrict__ x,
    const float* __restrict__ Wq,
    const float* __restrict__ Wk)
{
    __shared__ float As[2][128][20];
    __shared__ float Bs[2][16][136];

    const int b = blockIdx.z;
    const int col0 = blockIdx.x * 128;
    const float* xb = x + (size_t)b * CC * NN;

    const int tid = threadIdx.x, lane = tid & 31, warp = tid >> 5;
    const int gid = lane >> 2, tig = lane & 3;
    const int mw = (warp >> 2) * 64, nw = (warp & 3) * 32;

    const int am0 = tid >> 2;
    const int ak  = (tid & 3) * 4;
    const float* arow0 = Wq + (size_t)am0 * CC;
    const float* arow1 = Wk + (size_t)am0 * CC;
    const int bk0 = tid >> 5;
    const int bn  = (tid & 31) * 4;

    float4 c[4][4];
#pragma unroll
    for (int f = 0; f < 4; f++)
#pragma unroll
        for (int g = 0; g < 4; g++) c[f][g] = make_float4(0, 0, 0, 0);

    cp16(&As[0][am0][ak],       arow0 + ak);
    cp16(&As[0][am0 + 64][ak],  arow1 + ak);
    cp16(&Bs[0][bk0][bn],       xb + (size_t)bk0 * NN + col0 + bn);
    cp16(&Bs[0][bk0 + 8][bn],   xb + (size_t)(bk0 + 8) * NN + col0 + bn);
    CP_COMMIT();
    CP_WAIT0();
    __syncthreads();

    const int NS = CC / 16;
    for (int s = 0; s < NS; s++) {
        const int buf = s & 1;
        if (s + 1 < NS) {
            const int kc = (s + 1) * 16;
            const int nb = buf ^ 1;
            cp16(&As[nb][am0][ak],      arow0 + kc + ak);
            cp16(&As[nb][am0 + 64][ak], arow1 + kc + ak);
            cp16(&Bs[nb][bk0][bn],      xb + (size_t)(kc + bk0) * NN + col0 + bn);
            cp16(&Bs[nb][bk0 + 8][bn],  xb + (size_t)(kc + bk0 + 8) * NN + col0 + bn);
            CP_COMMIT();
        }
        compute_split_mA(As[buf], Bs[buf], c, gid, tig, mw, nw);
        CP_WAIT0();
        __syncthreads();
    }

    float* yb = d_Y + (size_t)b * 128 * NN;
#pragma unroll
    for (int f = 0; f < 4; f++) {
        const int r = mw + f * 16 + gid;
#pragma unroll
        for (int g = 0; g < 4; g++) {
            const int col = col0 + nw + g * 8 + 2 * tig;
            *(float2*)(yb + (size_t)r * NN + col)       = make_float2(c[f][g].x, c[f][g].y);
            *(float2*)(yb + (size_t)(r + 8) * NN + col) = make_float2(c[f][g].z, c[f][g].w);
        }
    }
}

// ---------------------------------------------------------------------------
// K1b: h' = (Wvr @ xr) * mask[col], stored bf16 with pair-perm cols.
// Inner: tf32 raw packed-A (round-15 proven). Epilogue: bf16x2 pair stores.
// pos within 16-block for pair (col,col+1): 4*tig + 2*(g&1).
// ---------------------------------------------------------------------------
__global__ __launch_bounds__(256, 2) void qkv_h_gemm(const float* __restrict__ mask)
{
    __shared__ float As[2][128][16];
    __shared__ float Bs[2][16][136];

    const int b = blockIdx.z;
    const int row0 = blockIdx.y * 128;
    const int col0 = blockIdx.x * 128;
    const float* xb = d_xr + (size_t)b * CC * NN;

    const int tid = threadIdx.x, lane = tid & 31, warp = tid >> 5;
    const int gid = lane >> 2, tig = lane & 3;
    const int mw = (warp >> 2) * 64, nw = (warp & 3) * 32;

    const int am0 = tid >> 2;
    const int ak  = (tid & 3) * 4;
    const float* arow0 = d_Wvr + (size_t)(row0 + am0) * CC;
    const float* arow1 = d_Wvr + (size_t)(row0 + am0 + 64) * CC;
    const int bk0 = tid >> 5;
    const int bn  = (tid & 31) * 4;

    float4 c[4][4];
#pragma unroll
    for (int f = 0; f < 4; f++)
#pragma unroll
        for (int g = 0; g < 4; g++) c[f][g] = make_float4(0, 0, 0, 0);

    cp16(&As[0][am0][ak],      arow0 + ak);
    cp16(&As[0][am0 + 64][ak], arow1 + ak);
    cp16(&Bs[0][bk0][bn],      xb + (size_t)bk0 * NN + col0 + bn);
    cp16(&Bs[0][bk0 + 8][bn],  xb + (size_t)(bk0 + 8) * NN + col0 + bn);
    CP_COMMIT();
    CP_WAIT0();
    __syncthreads();

    const int NS = CC / 16;
    for (int s = 0; s < NS; s++) {
        const int buf = s & 1;
        if (s + 1 < NS) {
            const int kc = (s + 1) * 16;
            const int nb = buf ^ 1;
            cp16(&As[nb][am0][ak],      arow0 + kc + ak);
            cp16(&As[nb][am0 + 64][ak], arow1 + kc + ak);
            cp16(&Bs[nb][bk0][bn],      xb + (size_t)(kc + bk0) * NN + col0 + bn);
            cp16(&Bs[nb][bk0 + 8][bn],  xb + (size_t)(kc + bk0 + 8) * NN + col0 + bn);
            CP_COMMIT();
        }
        compute_rawP(As[buf], Bs[buf], c, gid, tig, mw, nw);
        CP_WAIT0();
        __syncthreads();
    }

    __nv_bfloat16* hb = d_Hb + ((size_t)b * CC + row0) * NN;
    const float* mb = mask + (size_t)b * NN;
#pragma unroll
    for (int f = 0; f < 4; f++) {
        const int r = mw + f * 16 + gid;
#pragma unroll
        for (int g = 0; g < 4; g++) {
            const int col = col0 + nw + g * 8 + 2 * tig;
            float2 mv = *(const float2*)(mb + col);
            const int pg = col0 + nw + (g >> 1) * 16 + 4 * tig + 2 * (g & 1);
            __nv_bfloat162 p0 = __floats2bfloat162_rn(c[f][g].x * mv.x, c[f][g].y * mv.y);
            __nv_bfloat162 p1 = __floats2bfloat162_rn(c[f][g].z * mv.x, c[f][g].w * mv.y);
            *(__nv_bfloat162*)(hb + (size_t)r * NN + pg)       = p0;
            *(__nv_bfloat162*)(hb + (size_t)(r + 8) * NN + pg) = p1;
        }
    }
}

// ---------------------------------------------------------------------------
// K2: T[j][i] = exp(leaky(sum_q G[q][j] F[q][i])) = E[i][j], bf16 pair-perm.
// SPLIT tf32; A <- G (j = M dim), B <- F (i = N dim).
// Row sums: Z[j] = sum_i T[j][i], Sm[j] = sum_i mask[i]*T[j][i] (fp32, exact).
// ---------------------------------------------------------------------------
__global__ __launch_bounds__(256, 2) void scores_gemm_T(const float* __restrict__ mask)
{
    __shared__ float As[2][16][136];
    __shared__ float Bs[2][16][136];
    __shared__ float sZ[128];
    __shared__ float sSm[128];

    const int b  = blockIdx.z;
    const int it = blockIdx.x;
    const int i0 = it * 128;
    const int j0 = blockIdx.y * 128;
    const float* F = d_Y + (size_t)b * 128 * NN;
    const float* G = F + (size_t)CQ * NN;

    const int tid = threadIdx.x, lane = tid & 31, warp = tid >> 5;
    const int gid = lane >> 2, tig = lane & 3;
    const int mw = (warp >> 2) * 64, nw = (warp & 3) * 32;
    const int bk0 = tid >> 5;
    const int bn  = (tid & 31) * 4;

    if (tid < 128) { sZ[tid] = 0.0f; sSm[tid] = 0.0f; }

    float4 c[4][4];
#pragma unroll
    for (int f = 0; f < 4; f++)
#pragma unroll
        for (int g = 0; g < 4; g++) c[f][g] = make_float4(0, 0, 0, 0);

    // A <- G (j side), B <- F (i side)
    cp16(&As[0][bk0][bn],     G + (size_t)bk0 * NN + j0 + bn);
    cp16(&As[0][bk0 + 8][bn], G + (size_t)(bk0 + 8) * NN + j0 + bn);
    cp16(&Bs[0][bk0][bn],     F + (size_t)bk0 * NN + i0 + bn);
    cp16(&Bs[0][bk0 + 8][bn], F + (size_t)(bk0 + 8) * NN + i0 + bn);
    CP_COMMIT();
    CP_WAIT0();
    __syncthreads();

    const int NS = CQ / 16;  // 4
    for (int s = 0; s < NS; s++) {
        const int buf = s & 1;
        if (s + 1 < NS) {
            const int kc = (s + 1) * 16;
            const int nb = buf ^ 1;
            cp16(&As[nb][bk0][bn],     G + (size_t)(kc + bk0) * NN + j0 + bn);
            cp16(&As[nb][bk0 + 8][bn], G + (size_t)(kc + bk0 + 8) * NN + j0 + bn);
            cp16(&Bs[nb][bk0][bn],     F + (size_t)(kc + bk0) * NN + i0 + bn);
            cp16(&Bs[nb][bk0 + 8][bn], F + (size_t)(kc + bk0 + 8) * NN + i0 + bn);
            CP_COMMIT();
        }
        compute_split_kA(As[buf], Bs[buf], c, gid, tig, mw, nw);
        CP_WAIT0();
        __syncthreads();
    }

    __nv_bfloat16* T = d_T + (size_t)b * NN * NN;
    const float* mb = mask + (size_t)b * NN;

    float mcol[4][2];
#pragma unroll
    for (int g = 0; g < 4; g++) {
        const int icol = i0 + nw + g * 8 + 2 * tig;
        mcol[g][0] = __ldg(&mb[icol]);
        mcol[g][1] = __ldg(&mb[icol + 1]);
    }

    float zrow[4][2] = {{0, 0}, {0, 0}, {0, 0}, {0, 0}};
    float smrow[4][2] = {{0, 0}, {0, 0}, {0, 0}, {0, 0}};

#pragma unroll
    for (int f = 0; f < 4; f++) {
        const int jr = j0 + mw + f * 16 + gid;
#pragma unroll
        for (int g = 0; g < 4; g++) {
            float s0 = c[f][g].x, s1 = c[f][g].y, s2 = c[f][g].z, s3 = c[f][g].w;
            s0 = s0 >= 0.0f ? s0 : 0.2f * s0;
            s1 = s1 >= 0.0f ? s1 : 0.2f * s1;
            s2 = s2 >= 0.0f ? s2 : 0.2f * s2;
            s3 = s3 >= 0.0f ? s3 : 0.2f * s3;
            float e0 = __expf(fminf(s0, 75.0f));
            float e1 = __expf(fminf(s1, 75.0f));
            float e2 = __expf(fminf(s2, 75.0f));
            float e3 = __expf(fminf(s3, 75.0f));
            const int pg = i0 + nw + (g >> 1) * 16 + 4 * tig + 2 * (g & 1);
            __nv_bfloat162 p0 = __floats2bfloat162_rn(e0, e1);
            __nv_bfloat162 p1 = __floats2bfloat162_rn(e2, e3);
            *(__nv_bfloat162*)(T + (size_t)jr * NN + pg)       = p0;
            *(__nv_bfloat162*)(T + (size_t)(jr + 8) * NN + pg) = p1;
            zrow[f][0] += e0 + e1;                      zrow[f][1] += e2 + e3;
            smrow[f][0] += mcol[g][0] * e0 + mcol[g][1] * e1;
            smrow[f][1] += mcol[g][0] * e2 + mcol[g][1] * e3;
        }
    }

    // reduce over the 4 tig lanes sharing each row, then combine warps
#pragma unroll
    for (int f = 0; f < 4; f++) {
#pragma unroll
        for (int h = 0; h < 2; h++) {
            float z = zrow[f][h], sm = smrow[f][h];
            z += __shfl_xor_sync(0xffffffff, z, 1);
            z += __shfl_xor_sync(0xffffffff, z, 2);
            sm += __shfl_xor_sync(0xffffffff, sm, 1);
            sm += __shfl_xor_sync(0xffffffff, sm, 2);
            if (tig == 0) {
                const int rl = mw + f * 16 + gid + 8 * h;
                atomicAdd(&sZ[rl], z);
                atomicAdd(&sSm[rl], sm);
            }
        }
    }
    __syncthreads();
    if (tid < 128) {
        const size_t off = ((size_t)b * 8 + it) * NN + j0 + tid;
        d_partZ[off]  = sZ[tid];
        d_partSm[off] = sSm[tid];
    }
}

// ---------------------------------------------------------------------------
// K2b: fold 8 i-tile partials into per-j sums.
// ---------------------------------------------------------------------------
__global__ __launch_bounds__(256) void reduce_sums()
{
    const int b = blockIdx.y;
    const int j = blockIdx.x * 256 + threadIdx.x;
    float z = 0.0f, s = 0.0f;
#pragma unroll
    for (int t = 0; t < 8; t++) {
        const size_t off = ((size_t)b * 8 + t) * NN + j;
        z += d_partZ[off];
        s += d_partSm[off];
    }
    d_colZ[(size_t)b * NN + j]  = z;
    d_colSm[(size_t)b * NN + j] = s;
}

// ---------------------------------------------------------------------------
// K4: bf16 m16n8k16 GEMM.
// out[c][m] = gamma * (sum_n h'[c][n] * T[m][n]) * mask[m]/(Sm[m]+eps*Z[m]) + x[c][m]
// A = Hb[c][n] (bf16, pair-perm), B = T[m][n] (bf16, pair-perm): both k-major.
// smem [128][16] bf16 (32B rows) -> LDS.64 fragments; 16 MMA / chunk16 / warp.
// ---------------------------------------------------------------------------
__global__ __launch_bounds__(256, 2) void out_gemm_bf(
    const float* __restrict__ x,
    const float* __restrict__ mask,
    const float* __restrict__ gamma,
    float* __restrict__ out)
{
    __shared__ __align__(16) __nv_bfloat16 As[2][128][16];
    __shared__ __align__(16) __nv_bfloat16 Bs[2][128][16];

    const int b  = blockIdx.z;
    const int c0 = blockIdx.y * 128;
    const int m0 = blockIdx.x * 128;
    const __nv_bfloat16* Ah = d_Hb + ((size_t)b * CC + c0) * NN;
    const __nv_bfloat16* Bt = d_T + ((size_t)b * NN + m0) * NN;

    const int tid = threadIdx.x, lane = tid & 31, warp = tid >> 5;
    const int gid = lane >> 2, tig = lane & 3;
    const int mw = (warp >> 2) * 64, nw = (warp & 3) * 32;

    const int crow = tid >> 1;          // 0..127
    const int half = (tid & 1) * 8;     // 0 or 8 bf16

    float4 c[4][4];
#pragma unroll
    for (int f = 0; f < 4; f++)
#pragma unroll
        for (int g = 0; g < 4; g++) c[f][g] = make_float4(0, 0, 0, 0);

    cp16(&As[0][crow][half], Ah + (size_t)crow * NN + half);
    cp16(&Bs[0][crow][half], Bt + (size_t)crow * NN + half);
    CP_COMMIT();
    CP_WAIT0();
    __syncthreads();

    const int NS = NN / 16;  // 64
    for (int s = 0; s < NS; s++) {
        const int buf = s & 1;
        if (s + 1 < NS) {
            const int kc = (s + 1) * 16;
            const int nb = buf ^ 1;
            cp16(&As[nb][crow][half], Ah + (size_t)crow * NN + kc + half);
            cp16(&Bs[nb][crow][half], Bt + (size_t)crow * NN + kc + half);
            CP_COMMIT();
        }
        // compute on buf
        {
            uint32_t bfr[4][2];
#pragma unroll
            for (int g = 0; g < 4; g++) {
                const int n0 = nw + g * 8 + gid;
                uint2 q = *(const uint2*)&Bs[buf][n0][tig * 4];
                bfr[g][0] = q.x;   // k = 2t, 2t+1
                bfr[g][1] = q.y;   // k = 2t+8, 2t+9
            }
#pragma unroll
            for (int f = 0; f < 4; f++) {
                const int r = mw + f * 16 + gid;
                uint2 qa0 = *(const uint2*)&As[buf][r][tig * 4];
                uint2 qa1 = *(const uint2*)&As[buf][r + 8][tig * 4];
                uint32_t a[4] = { qa0.x, qa1.x, qa0.y, qa1.y };
#pragma unroll
                for (int g = 0; g < 4; g++)
                    mma16(c[f][g], a, bfr[g]);
            }
        }
        CP_WAIT0();
        __syncthreads();
    }

    const float g0 = gamma[0];
    const float* xb = x + (size_t)b * CC * NN;
    float* ob = out + (size_t)b * CC * NN;
    const float* mb = mask + (size_t)b * NN;
    const float* zc = d_colZ + (size_t)b * NN;
    const float* sc = d_colSm + (size_t)b * NN;

#pragma unroll
    for (int g = 0; g < 4; g++) {
        const int col = m0 + nw + g * 8 + 2 * tig;
        float2 mv = *(const float2*)(mb + col);
        float2 zv = *(const float2*)(zc + col);
        float2 sv = *(const float2*)(sc + col);
        const float w0 = g0 * mv.x / (sv.x + 1e-6f * zv.x);
        const float w1 = g0 * mv.y / (sv.y + 1e-6f * zv.y);
#pragma unroll
        for (int f = 0; f < 4; f++) {
            const int r = c0 + mw + f * 16 + gid;
            float2 x0 = *(const float2*)(xb + (size_t)r * NN + col);
            float2 x1 = *(const float2*)(xb + (size_t)(r + 8) * NN + col);
            float2 o0, o1;
            o0.x = c[f][g].x * w0 + x0.x;
            o0.y = c[f][g].y * w1 + x0.y;
            o1.x = c[f][g].z * w0 + x1.x;
            o1.y = c[f][g].w * w1 + x1.y;
            *(float2*)(ob + (size_t)r * NN + col)       = o0;
            *(float2*)(ob + (size_t)(r + 8) * NN + col) = o1;
        }
    }
}

// ---------------------------------------------------------------------------
// Launch: fork the h'-chain onto a second stream (overlaps fg -> scores ->
// reduce); join before out_gemm.
// ---------------------------------------------------------------------------
extern "C" void kernel_launch(void* const* d_in, const int* in_sizes, int n_in,
                              void* d_out, int out_size)
{
    const float* x     = (const float*)d_in[0];
    const float* mask  = (const float*)d_in[1];
    const float* Wq    = (const float*)d_in[2];
    const float* Wk    = (const float*)d_in[3];
    const float* Wv    = (const float*)d_in[4];
    const float* gamma = (const float*)d_in[5];
    float* out = (float*)d_out;

    static cudaStream_t s2 = nullptr;
    static cudaEvent_t evFork = nullptr, evJoin = nullptr;
    if (s2 == nullptr) {
        cudaStreamCreateWithFlags(&s2, cudaStreamNonBlocking);
        cudaEventCreateWithFlags(&evFork, cudaEventDisableTiming);
        cudaEventCreateWithFlags(&evJoin, cudaEventDisableTiming);
    }

    // fork
    cudaEventRecord(evFork, 0);
    cudaStreamWaitEvent(s2, evFork, 0);

    // stream s2: h' chain
    round_x_kernel <<<(size_t)BB * CC * NN / (256 * 4), 256, 0, s2>>>(x);
    round_wv_kernel<<<(size_t)CC * CC / (256 * 4), 256, 0, s2>>>(Wv);
    qkv_h_gemm<<<dim3(NN / 128, CC / 128, BB), 256, 0, s2>>>(mask);
    cudaEventRecord(evJoin, s2);

    // stream 0: fg -> scores(T) -> reduce
    qkv_fg_gemm<<<dim3(NN / 128, 1, BB), 256>>>(x, Wq, Wk);
    scores_gemm_T<<<dim3(NN / 128, NN / 128, BB), 256>>>(mask);
    reduce_sums<<<dim3(NN / 256, BB), 256>>>();

    // join, then the output GEMM
    cudaStreamWaitEvent(0, evJoin, 0);
    out_gemm_bf<<<dim3(NN / 128, CC / 128, BB), 256>>>(x, mask, gamma, out);
}

// round 17
// speedup vs baseline: 2.4144x; 1.0548x over previous
#include <cuda_runtime.h>
#include <cuda_bf16.h>
#include <cstdint>

// Problem dims (fixed by the dataset)
#define BB   64
#define CC   512
#define NN   1024
#define CQ   64

// Scratch
__device__ float d_Y[(size_t)BB * 128 * NN];            // f rows 0..63, g rows 64..127
__device__ float d_xr[(size_t)BB * CC * NN];            // x rounded to tf32 (rna)
__device__ float d_Wvr[(size_t)CC * CC];                // Wv tf32, fp32-kperm
__device__ __nv_bfloat16 d_Hb[(size_t)BB * CC * NN];    // h' bf16, pair-perm cols
__device__ __nv_bfloat16 d_T[(size_t)BB * NN * NN];     // T[j][i] = E[i][j], bf16 pair-perm
__device__ float d_partZ[(size_t)BB * 8 * NN];
__device__ float d_partSm[(size_t)BB * 8 * NN];
__device__ float d_colZ[(size_t)BB * NN];
__device__ float d_colSm[(size_t)BB * NN];

// ---------------------------------------------------------------------------
// helpers
// ---------------------------------------------------------------------------
__device__ __forceinline__ uint32_t f2tf(float f) {
    uint32_t u;
    asm("cvt.rna.tf32.f32 %0, %1;" : "=r"(u) : "f"(f));
    return u;
}

// fp32 k-permutation within 16-blocks (round-14 proven, for Wvr LDS.128):
__device__ __forceinline__ int kperm(int c) {
    return (c & ~15) | (((c & 3) << 2) | ((c & 15) >> 2));
}

__device__ __forceinline__ void mma8(float4& d, const uint32_t a[4], const uint32_t b[2]) {
    asm volatile(
        "mma.sync.aligned.m16n8k8.row.col.f32.tf32.tf32.f32 "
        "{%0,%1,%2,%3}, {%4,%5,%6,%7}, {%8,%9}, {%0,%1,%2,%3};"
        : "+f"(d.x), "+f"(d.y), "+f"(d.z), "+f"(d.w)
        : "r"(a[0]), "r"(a[1]), "r"(a[2]), "r"(a[3]), "r"(b[0]), "r"(b[1]));
}

__device__ __forceinline__ void mma16(float4& d, const uint32_t a[4], const uint32_t b[2]) {
    asm volatile(
        "mma.sync.aligned.m16n8k16.row.col.f32.bf16.bf16.f32 "
        "{%0,%1,%2,%3}, {%4,%5,%6,%7}, {%8,%9}, {%0,%1,%2,%3};"
        : "+f"(d.x), "+f"(d.y), "+f"(d.z), "+f"(d.w)
        : "r"(a[0]), "r"(a[1]), "r"(a[2]), "r"(a[3]), "r"(b[0]), "r"(b[1]));
}

__device__ __forceinline__ void cp16(void* dst_smem, const void* src_gmem) {
    uint32_t d = (uint32_t)__cvta_generic_to_shared(dst_smem);
    asm volatile("cp.async.cg.shared.global [%0], [%1], 16;" :: "r"(d), "l"(src_gmem));
}
#define CP_COMMIT() asm volatile("cp.async.commit_group;")
#define CP_WAIT0()  asm volatile("cp.async.wait_group 0;")
#define CP_WAIT1()  asm volatile("cp.async.wait_group 1;")

// ---------------------------------------------------------------------------
// fp32 packed-A raw tf32 compute (round-15 proven): A [128][16] fp32 kperm,
// B [16][136].
// ---------------------------------------------------------------------------
__device__ __forceinline__ void compute_rawP(
    const float (*As)[16], const float (*Bs)[136],
    float4 (&c)[4][4], int gid, int tig, int mw, int nw)
{
    uint32_t bfr[2][4][2];
#pragma unroll
    for (int ks2 = 0; ks2 < 2; ks2++)
#pragma unroll
        for (int g = 0; g < 4; g++) {
            const int n0 = nw + g * 8 + gid;
            bfr[ks2][g][0] = __float_as_uint(Bs[8 * ks2 + tig][n0]);
            bfr[ks2][g][1] = __float_as_uint(Bs[8 * ks2 + tig + 4][n0]);
        }
#pragma unroll
    for (int f = 0; f < 4; f++) {
        const int r = mw + f * 16 + gid;
        float4 qa0 = *(const float4*)&As[r][tig * 4];
        float4 qa1 = *(const float4*)&As[r + 8][tig * 4];
        uint32_t a0[4] = { __float_as_uint(qa0.x), __float_as_uint(qa1.x),
                           __float_as_uint(qa0.y), __float_as_uint(qa1.y) };
        uint32_t a8[4] = { __float_as_uint(qa0.z), __float_as_uint(qa1.z),
                           __float_as_uint(qa0.w), __float_as_uint(qa1.w) };
#pragma unroll
        for (int g = 0; g < 4; g++) {
            mma8(c[f][g], a0, bfr[0][g]);
            mma8(c[f][g], a8, bfr[1][g]);
        }
    }
}

// ---------------------------------------------------------------------------
// Split (3xTF32) computes — proven, unchanged.
// ---------------------------------------------------------------------------
__device__ __forceinline__ void compute_split_mA(
    const float (*As)[20], const float (*Bs)[136],
    float4 (&c)[4][4], int gid, int tig, int mw, int nw)
{
#pragma unroll
    for (int ks = 0; ks < 16; ks += 8) {
        uint32_t ahi[4][4], alo[4][4];
        uint32_t bhi[4][2], blo[4][2];
#pragma unroll
        for (int f = 0; f < 4; f++) {
            const int r = mw + f * 16 + gid;
            float a0 = As[r][ks + tig];
            float a1 = As[r + 8][ks + tig];
            float a2 = As[r][ks + tig + 4];
            float a3 = As[r + 8][ks + tig + 4];
            ahi[f][0] = f2tf(a0); ahi[f][1] = f2tf(a1);
            ahi[f][2] = f2tf(a2); ahi[f][3] = f2tf(a3);
            alo[f][0] = f2tf(a0 - __uint_as_float(ahi[f][0]));
            alo[f][1] = f2tf(a1 - __uint_as_float(ahi[f][1]));
            alo[f][2] = f2tf(a2 - __uint_as_float(ahi[f][2]));
            alo[f][3] = f2tf(a3 - __uint_as_float(ahi[f][3]));
        }
#pragma unroll
        for (int g = 0; g < 4; g++) {
            const int n0 = nw + g * 8 + gid;
            float b0 = Bs[ks + tig][n0];
            float b1 = Bs[ks + tig + 4][n0];
            bhi[g][0] = f2tf(b0); bhi[g][1] = f2tf(b1);
            blo[g][0] = f2tf(b0 - __uint_as_float(bhi[g][0]));
            blo[g][1] = f2tf(b1 - __uint_as_float(bhi[g][1]));
        }
#pragma unroll
        for (int f = 0; f < 4; f++)
#pragma unroll
            for (int g = 0; g < 4; g++) {
                mma8(c[f][g], ahi[f], blo[g]);
                mma8(c[f][g], alo[f], bhi[g]);
                mma8(c[f][g], ahi[f], bhi[g]);
            }
    }
}

__device__ __forceinline__ void compute_split_kA(
    const float (*As)[136], const float (*Bs)[136],
    float4 (&c)[4][4], int gid, int tig, int mw, int nw)
{
#pragma unroll
    for (int ks = 0; ks < 16; ks += 8) {
        uint32_t ahi[4][4], alo[4][4];
        uint32_t bhi[4][2], blo[4][2];
#pragma unroll
        for (int f = 0; f < 4; f++) {
            const int r = mw + f * 16 + gid;
            float a0 = As[ks + tig][r];
            float a1 = As[ks + tig][r + 8];
            float a2 = As[ks + tig + 4][r];
            float a3 = As[ks + tig + 4][r + 8];
            ahi[f][0] = f2tf(a0); ahi[f][1] = f2tf(a1);
            ahi[f][2] = f2tf(a2); ahi[f][3] = f2tf(a3);
            alo[f][0] = f2tf(a0 - __uint_as_float(ahi[f][0]));
            alo[f][1] = f2tf(a1 - __uint_as_float(ahi[f][1]));
            alo[f][2] = f2tf(a2 - __uint_as_float(ahi[f][2]));
            alo[f][3] = f2tf(a3 - __uint_as_float(ahi[f][3]));
        }
#pragma unroll
        for (int g = 0; g < 4; g++) {
            const int n0 = nw + g * 8 + gid;
            float b0 = Bs[ks + tig][n0];
            float b1 = Bs[ks + tig + 4][n0];
            bhi[g][0] = f2tf(b0); bhi[g][1] = f2tf(b1);
            blo[g][0] = f2tf(b0 - __uint_as_float(bhi[g][0]));
            blo[g][1] = f2tf(b1 - __uint_as_float(bhi[g][1]));
        }
#pragma unroll
        for (int f = 0; f < 4; f++)
#pragma unroll
            for (int g = 0; g < 4; g++) {
                mma8(c[f][g], ahi[f], blo[g]);
                mma8(c[f][g], alo[f], bhi[g]);
                mma8(c[f][g], ahi[f], bhi[g]);
            }
    }
}

// ---------------------------------------------------------------------------
// K0: round x (plain) and Wv (fp32-kperm) to tf32 once.
// ---------------------------------------------------------------------------
__global__ __launch_bounds__(256) void round_x_kernel(const float* __restrict__ x)
{
    const size_t i = ((size_t)blockIdx.x * 256 + threadIdx.x) * 4;
    float4 v = *(const float4*)(x + i);
    v.x = __uint_as_float(f2tf(v.x));
    v.y = __uint_as_float(f2tf(v.y));
    v.z = __uint_as_float(f2tf(v.z));
    v.w = __uint_as_float(f2tf(v.w));
    *(float4*)(d_xr + i) = v;
}

__global__ __launch_bounds__(256) void round_wv_kernel(const float* __restrict__ Wv)
{
    const size_t i = ((size_t)blockIdx.x * 256 + threadIdx.x) * 4;
    const size_t row = i / CC;
    const int cb = (int)(i % CC);
    float4 v = *(const float4*)(Wv + i);
    float vr[4];
    vr[0] = __uint_as_float(f2tf(v.x));
    vr[1] = __uint_as_float(f2tf(v.y));
    vr[2] = __uint_as_float(f2tf(v.z));
    vr[3] = __uint_as_float(f2tf(v.w));
    float* drow = d_Wvr + row * CC;
#pragma unroll
    for (int j = 0; j < 4; j++)
        drow[kperm(cb + j)] = vr[j];
}

// ---------------------------------------------------------------------------
// K1a: f,g projection = [Wq;Wk] @ x.  SPLIT tf32, cp.async. (proven)
// ---------------------------------------------------------------------------
__global__ __launch_bounds__(256, 2) void qkv_fg_gemm(
    const float* __restrict__ x,
    const float* __restrict__ Wq,
    const float* __restrict__ Wk)
{
    __shared__ float As[2][128][20];
    __shared__ float Bs[2][16][136];

    const int b = blockIdx.z;
    const int col0 = blockIdx.x * 128;
    const float* xb = x + (size_t)b * CC * NN;

    const int tid = threadIdx.x, lane = tid & 31, warp = tid >> 5;
    const int gid = lane >> 2, tig = lane & 3;
    const int mw = (warp >> 2) * 64, nw = (warp & 3) * 32;

    const int am0 = tid >> 2;
    const int ak  = (tid & 3) * 4;
    const float* arow0 = Wq + (size_t)am0 * CC;
    const float* arow1 = Wk + (size_t)am0 * CC;
    const int bk0 = tid >> 5;
    const int bn  = (tid & 31) * 4;

    float4 c[4][4];
#pragma unroll
    for (int f = 0; f < 4; f++)
#pragma unroll
        for (int g = 0; g < 4; g++) c[f][g] = make_float4(0, 0, 0, 0);

    cp16(&As[0][am0][ak],       arow0 + ak);
    cp16(&As[0][am0 + 64][ak],  arow1 + ak);
    cp16(&Bs[0][bk0][bn],       xb + (size_t)bk0 * NN + col0 + bn);
    cp16(&Bs[0][bk0 + 8][bn],   xb + (size_t)(bk0 + 8) * NN + col0 + bn);
    CP_COMMIT();
    CP_WAIT0();
    __syncthreads();

    const int NS = CC / 16;
    for (int s = 0; s < NS; s++) {
        const int buf = s & 1;
        if (s + 1 < NS) {
            const int kc = (s + 1) * 16;
            const int nb = buf ^ 1;
            cp16(&As[nb][am0][ak],      arow0 + kc + ak);
            cp16(&As[nb][am0 + 64][ak], arow1 + kc + ak);
            cp16(&Bs[nb][bk0][bn],      xb + (size_t)(kc + bk0) * NN + col0 + bn);
            cp16(&Bs[nb][bk0 + 8][bn],  xb + (size_t)(kc + bk0 + 8) * NN + col0 + bn);
            CP_COMMIT();
        }
        compute_split_mA(As[buf], Bs[buf], c, gid, tig, mw, nw);
        CP_WAIT0();
        __syncthreads();
    }

    float* yb = d_Y + (size_t)b * 128 * NN;
#pragma unroll
    for (int f = 0; f < 4; f++) {
        const int r = mw + f * 16 + gid;
#pragma unroll
        for (int g = 0; g < 4; g++) {
            const int col = col0 + nw + g * 8 + 2 * tig;
            *(float2*)(yb + (size_t)r * NN + col)       = make_float2(c[f][g].x, c[f][g].y);
            *(float2*)(yb + (size_t)(r + 8) * NN + col) = make_float2(c[f][g].z, c[f][g].w);
        }
    }
}

// ---------------------------------------------------------------------------
// K1b: h' = (Wvr @ xr) * mask[col], stored bf16 with pair-perm cols.
// ---------------------------------------------------------------------------
__global__ __launch_bounds__(256, 2) void qkv_h_gemm(const float* __restrict__ mask)
{
    __shared__ float As[2][128][16];
    __shared__ float Bs[2][16][136];

    const int b = blockIdx.z;
    const int row0 = blockIdx.y * 128;
    const int col0 = blockIdx.x * 128;
    const float* xb = d_xr + (size_t)b * CC * NN;

    const int tid = threadIdx.x, lane = tid & 31, warp = tid >> 5;
    const int gid = lane >> 2, tig = lane & 3;
    const int mw = (warp >> 2) * 64, nw = (warp & 3) * 32;

    const int am0 = tid >> 2;
    const int ak  = (tid & 3) * 4;
    const float* arow0 = d_Wvr + (size_t)(row0 + am0) * CC;
    const float* arow1 = d_Wvr + (size_t)(row0 + am0 + 64) * CC;
    const int bk0 = tid >> 5;
    const int bn  = (tid & 31) * 4;

    float4 c[4][4];
#pragma unroll
    for (int f = 0; f < 4; f++)
#pragma unroll
        for (int g = 0; g < 4; g++) c[f][g] = make_float4(0, 0, 0, 0);

    cp16(&As[0][am0][ak],      arow0 + ak);
    cp16(&As[0][am0 + 64][ak], arow1 + ak);
    cp16(&Bs[0][bk0][bn],      xb + (size_t)bk0 * NN + col0 + bn);
    cp16(&Bs[0][bk0 + 8][bn],  xb + (size_t)(bk0 + 8) * NN + col0 + bn);
    CP_COMMIT();
    CP_WAIT0();
    __syncthreads();

    const int NS = CC / 16;
    for (int s = 0; s < NS; s++) {
        const int buf = s & 1;
        if (s + 1 < NS) {
            const int kc = (s + 1) * 16;
            const int nb = buf ^ 1;
            cp16(&As[nb][am0][ak],      arow0 + kc + ak);
            cp16(&As[nb][am0 + 64][ak], arow1 + kc + ak);
            cp16(&Bs[nb][bk0][bn],      xb + (size_t)(kc + bk0) * NN + col0 + bn);
            cp16(&Bs[nb][bk0 + 8][bn],  xb + (size_t)(kc + bk0 + 8) * NN + col0 + bn);
            CP_COMMIT();
        }
        compute_rawP(As[buf], Bs[buf], c, gid, tig, mw, nw);
        CP_WAIT0();
        __syncthreads();
    }

    __nv_bfloat16* hb = d_Hb + ((size_t)b * CC + row0) * NN;
    const float* mb = mask + (size_t)b * NN;
#pragma unroll
    for (int f = 0; f < 4; f++) {
        const int r = mw + f * 16 + gid;
#pragma unroll
        for (int g = 0; g < 4; g++) {
            const int col = col0 + nw + g * 8 + 2 * tig;
            float2 mv = *(const float2*)(mb + col);
            const int pg = col0 + nw + (g >> 1) * 16 + 4 * tig + 2 * (g & 1);
            __nv_bfloat162 p0 = __floats2bfloat162_rn(c[f][g].x * mv.x, c[f][g].y * mv.y);
            __nv_bfloat162 p1 = __floats2bfloat162_rn(c[f][g].z * mv.x, c[f][g].w * mv.y);
            *(__nv_bfloat162*)(hb + (size_t)r * NN + pg)       = p0;
            *(__nv_bfloat162*)(hb + (size_t)(r + 8) * NN + pg) = p1;
        }
    }
}

// ---------------------------------------------------------------------------
// K2: T[j][i] = exp(leaky(sum_q G[q][j] F[q][i])) = E[i][j], bf16 pair-perm.
// Z/Sm accumulated from the BF16-ROUNDED values (consistent with stored T):
// for peaked softmax columns the dominant element's rounding error cancels
// between numerator and denominator.
// ---------------------------------------------------------------------------
__global__ __launch_bounds__(256, 2) void scores_gemm_T(const float* __restrict__ mask)
{
    __shared__ float As[2][16][136];
    __shared__ float Bs[2][16][136];
    __shared__ float sZ[128];
    __shared__ float sSm[128];

    const int b  = blockIdx.z;
    const int it = blockIdx.x;
    const int i0 = it * 128;
    const int j0 = blockIdx.y * 128;
    const float* F = d_Y + (size_t)b * 128 * NN;
    const float* G = F + (size_t)CQ * NN;

    const int tid = threadIdx.x, lane = tid & 31, warp = tid >> 5;
    const int gid = lane >> 2, tig = lane & 3;
    const int mw = (warp >> 2) * 64, nw = (warp & 3) * 32;
    const int bk0 = tid >> 5;
    const int bn  = (tid & 31) * 4;

    if (tid < 128) { sZ[tid] = 0.0f; sSm[tid] = 0.0f; }

    float4 c[4][4];
#pragma unroll
    for (int f = 0; f < 4; f++)
#pragma unroll
        for (int g = 0; g < 4; g++) c[f][g] = make_float4(0, 0, 0, 0);

    // A <- G (j side), B <- F (i side)
    cp16(&As[0][bk0][bn],     G + (size_t)bk0 * NN + j0 + bn);
    cp16(&As[0][bk0 + 8][bn], G + (size_t)(bk0 + 8) * NN + j0 + bn);
    cp16(&Bs[0][bk0][bn],     F + (size_t)bk0 * NN + i0 + bn);
    cp16(&Bs[0][bk0 + 8][bn], F + (size_t)(bk0 + 8) * NN + i0 + bn);
    CP_COMMIT();
    CP_WAIT0();
    __syncthreads();

    const int NS = CQ / 16;  // 4
    for (int s = 0; s < NS; s++) {
        const int buf = s & 1;
        if (s + 1 < NS) {
            const int kc = (s + 1) * 16;
            const int nb = buf ^ 1;
            cp16(&As[nb][bk0][bn],     G + (size_t)(kc + bk0) * NN + j0 + bn);
            cp16(&As[nb][bk0 + 8][bn], G + (size_t)(kc + bk0 + 8) * NN + j0 + bn);
            cp16(&Bs[nb][bk0][bn],     F + (size_t)(kc + bk0) * NN + i0 + bn);
            cp16(&Bs[nb][bk0 + 8][bn], F + (size_t)(kc + bk0 + 8) * NN + i0 + bn);
            CP_COMMIT();
        }
        compute_split_kA(As[buf], Bs[buf], c, gid, tig, mw, nw);
        CP_WAIT0();
        __syncthreads();
    }

    __nv_bfloat16* T = d_T + (size_t)b * NN * NN;
    const float* mb = mask + (size_t)b * NN;

    float mcol[4][2];
#pragma unroll
    for (int g = 0; g < 4; g++) {
        const int icol = i0 + nw + g * 8 + 2 * tig;
        mcol[g][0] = __ldg(&mb[icol]);
        mcol[g][1] = __ldg(&mb[icol + 1]);
    }

    float zrow[4][2] = {{0, 0}, {0, 0}, {0, 0}, {0, 0}};
    float smrow[4][2] = {{0, 0}, {0, 0}, {0, 0}, {0, 0}};

#pragma unroll
    for (int f = 0; f < 4; f++) {
        const int jr = j0 + mw + f * 16 + gid;
#pragma unroll
        for (int g = 0; g < 4; g++) {
            float s0 = c[f][g].x, s1 = c[f][g].y, s2 = c[f][g].z, s3 = c[f][g].w;
            s0 = s0 >= 0.0f ? s0 : 0.2f * s0;
            s1 = s1 >= 0.0f ? s1 : 0.2f * s1;
            s2 = s2 >= 0.0f ? s2 : 0.2f * s2;
            s3 = s3 >= 0.0f ? s3 : 0.2f * s3;
            float e0 = __expf(fminf(s0, 75.0f));
            float e1 = __expf(fminf(s1, 75.0f));
            float e2 = __expf(fminf(s2, 75.0f));
            float e3 = __expf(fminf(s3, 75.0f));
            const int pg = i0 + nw + (g >> 1) * 16 + 4 * tig + 2 * (g & 1);
            __nv_bfloat162 p0 = __floats2bfloat162_rn(e0, e1);
            __nv_bfloat162 p1 = __floats2bfloat162_rn(e2, e3);
            *(__nv_bfloat162*)(T + (size_t)jr * NN + pg)       = p0;
            *(__nv_bfloat162*)(T + (size_t)(jr + 8) * NN + pg) = p1;
            // accumulate the ROUNDED values -> denominator consistent with T
            float r0 = __bfloat162float(p0.x);
            float r1 = __bfloat162float(p0.y);
            float r2 = __bfloat162float(p1.x);
            float r3 = __bfloat162float(p1.y);
            zrow[f][0] += r0 + r1;                      zrow[f][1] += r2 + r3;
            smrow[f][0] += mcol[g][0] * r0 + mcol[g][1] * r1;
            smrow[f][1] += mcol[g][0] * r2 + mcol[g][1] * r3;
        }
    }

    // reduce over the 4 tig lanes sharing each row, then combine warps
#pragma unroll
    for (int f = 0; f < 4; f++) {
#pragma unroll
        for (int h = 0; h < 2; h++) {
            float z = zrow[f][h], sm = smrow[f][h];
            z += __shfl_xor_sync(0xffffffff, z, 1);
            z += __shfl_xor_sync(0xffffffff, z, 2);
            sm += __shfl_xor_sync(0xffffffff, sm, 1);
            sm += __shfl_xor_sync(0xffffffff, sm, 2);
            if (tig == 0) {
                const int rl = mw + f * 16 + gid + 8 * h;
                atomicAdd(&sZ[rl], z);
                atomicAdd(&sSm[rl], sm);
            }
        }
    }
    __syncthreads();
    if (tid < 128) {
        const size_t off = ((size_t)b * 8 + it) * NN + j0 + tid;
        d_partZ[off]  = sZ[tid];
        d_partSm[off] = sSm[tid];
    }
}

// ---------------------------------------------------------------------------
// K2b: fold 8 i-tile partials into per-j sums.
// ---------------------------------------------------------------------------
__global__ __launch_bounds__(256) void reduce_sums()
{
    const int b = blockIdx.y;
    const int j = blockIdx.x * 256 + threadIdx.x;
    float z = 0.0f, s = 0.0f;
#pragma unroll
    for (int t = 0; t < 8; t++) {
        const size_t off = ((size_t)b * 8 + t) * NN + j;
        z += d_partZ[off];
        s += d_partSm[off];
    }
    d_colZ[(size_t)b * NN + j]  = z;
    d_colSm[(size_t)b * NN + j] = s;
}

// ---------------------------------------------------------------------------
// K4: bf16 m16n8k16 GEMM, 3-stage cp.async pipeline.
// out[c][m] = gamma * (sum_n h'[c][n] * T[m][n]) * mask[m]/(Sm[m]+eps*Z[m]) + x[c][m]
// ---------------------------------------------------------------------------
__global__ __launch_bounds__(256, 2) void out_gemm_bf(
    const float* __restrict__ x,
    const float* __restrict__ mask,
    const float* __restrict__ gamma,
    float* __restrict__ out)
{
    __shared__ __align__(16) __nv_bfloat16 As[3][128][16];
    __shared__ __align__(16) __nv_bfloat16 Bs[3][128][16];

    const int b  = blockIdx.z;
    const int c0 = blockIdx.y * 128;
    const int m0 = blockIdx.x * 128;
    const __nv_bfloat16* Ah = d_Hb + ((size_t)b * CC + c0) * NN;
    const __nv_bfloat16* Bt = d_T + ((size_t)b * NN + m0) * NN;

    const int tid = threadIdx.x, lane = tid & 31, warp = tid >> 5;
    const int gid = lane >> 2, tig = lane & 3;
    const int mw = (warp >> 2) * 64, nw = (warp & 3) * 32;

    const int crow = tid >> 1;          // 0..127
    const int half = (tid & 1) * 8;     // 0 or 8 bf16

    float4 c[4][4];
#pragma unroll
    for (int f = 0; f < 4; f++)
#pragma unroll
        for (int g = 0; g < 4; g++) c[f][g] = make_float4(0, 0, 0, 0);

    // prologue: stage 0 and 1 in flight as separate groups
    cp16(&As[0][crow][half], Ah + (size_t)crow * NN + half);
    cp16(&Bs[0][crow][half], Bt + (size_t)crow * NN + half);
    CP_COMMIT();
    cp16(&As[1][crow][half], Ah + (size_t)crow * NN + 16 + half);
    cp16(&Bs[1][crow][half], Bt + (size_t)crow * NN + 16 + half);
    CP_COMMIT();

    const int NS = NN / 16;  // 64
    for (int s = 0; s < NS; s++) {
        const int buf = s % 3;
        CP_WAIT1();          // group for stage s complete (s+1 may fly)
        __syncthreads();     // also retires compute(s-1) before reusing its buffer
        if (s + 2 < NS) {
            const int kc = (s + 2) * 16;
            const int nb = (s + 2) % 3;
            cp16(&As[nb][crow][half], Ah + (size_t)crow * NN + kc + half);
            cp16(&Bs[nb][crow][half], Bt + (size_t)crow * NN + kc + half);
            CP_COMMIT();
        }
        // compute on buf
        {
            uint32_t bfr[4][2];
#pragma unroll
            for (int g = 0; g < 4; g++) {
                const int n0 = nw + g * 8 + gid;
                uint2 q = *(const uint2*)&Bs[buf][n0][tig * 4];
                bfr[g][0] = q.x;
                bfr[g][1] = q.y;
            }
#pragma unroll
            for (int f = 0; f < 4; f++) {
                const int r = mw + f * 16 + gid;
                uint2 qa0 = *(const uint2*)&As[buf][r][tig * 4];
                uint2 qa1 = *(const uint2*)&As[buf][r + 8][tig * 4];
                uint32_t a[4] = { qa0.x, qa1.x, qa0.y, qa1.y };
#pragma unroll
                for (int g = 0; g < 4; g++)
                    mma16(c[f][g], a, bfr[g]);
            }
        }
    }

    const float g0 = gamma[0];
    const float* xb = x + (size_t)b * CC * NN;
    float* ob = out + (size_t)b * CC * NN;
    const float* mb = mask + (size_t)b * NN;
    const float* zc = d_colZ + (size_t)b * NN;
    const float* sc = d_colSm + (size_t)b * NN;

#pragma unroll
    for (int g = 0; g < 4; g++) {
        const int col = m0 + nw + g * 8 + 2 * tig;
        float2 mv = *(const float2*)(mb + col);
        float2 zv = *(const float2*)(zc + col);
        float2 sv = *(const float2*)(sc + col);
        const float w0 = g0 * mv.x / (sv.x + 1e-6f * zv.x);
        const float w1 = g0 * mv.y / (sv.y + 1e-6f * zv.y);
#pragma unroll
        for (int f = 0; f < 4; f++) {
            const int r = c0 + mw + f * 16 + gid;
            float2 x0 = *(const float2*)(xb + (size_t)r * NN + col);
            float2 x1 = *(const float2*)(xb + (size_t)(r + 8) * NN + col);
            float2 o0, o1;
            o0.x = c[f][g].x * w0 + x0.x;
            o0.y = c[f][g].y * w1 + x0.y;
            o1.x = c[f][g].z * w0 + x1.x;
            o1.y = c[f][g].w * w1 + x1.y;
            *(float2*)(ob + (size_t)r * NN + col)       = o0;
            *(float2*)(ob + (size_t)(r + 8) * NN + col) = o1;
        }
    }
}

// ---------------------------------------------------------------------------
// Launch: fork the h'-chain onto a second stream (overlaps fg -> scores ->
// reduce); join before out_gemm.
// ---------------------------------------------------------------------------
extern "C" void kernel_launch(void* const* d_in, const int* in_sizes, int n_in,
                              void* d_out, int out_size)
{
    const float* x     = (const float*)d_in[0];
    const float* mask  = (const float*)d_in[1];
    const float* Wq    = (const float*)d_in[2];
    const float* Wk    = (const float*)d_in[3];
    const float* Wv    = (const float*)d_in[4];
    const float* gamma = (const float*)d_in[5];
    float* out = (float*)d_out;

    static cudaStream_t s2 = nullptr;
    static cudaEvent_t evFork = nullptr, evJoin = nullptr;
    if (s2 == nullptr) {
        cudaStreamCreateWithFlags(&s2, cudaStreamNonBlocking);
        cudaEventCreateWithFlags(&evFork, cudaEventDisableTiming);
        cudaEventCreateWithFlags(&evJoin, cudaEventDisableTiming);
    }

    // fork
    cudaEventRecord(evFork, 0);
    cudaStreamWaitEvent(s2, evFork, 0);

    // stream s2: h' chain
    round_x_kernel <<<(size_t)BB * CC * NN / (256 * 4), 256, 0, s2>>>(x);
    round_wv_kernel<<<(size_t)CC * CC / (256 * 4), 256, 0, s2>>>(Wv);
    qkv_h_gemm<<<dim3(NN / 128, CC / 128, BB), 256, 0, s2>>>(mask);
    cudaEventRecord(evJoin, s2);

    // stream 0: fg -> scores(T) -> reduce
    qkv_fg_gemm<<<dim3(NN / 128, 1, BB), 256>>>(x, Wq, Wk);
    scores_gemm_T<<<dim3(NN / 128, NN / 128, BB), 256>>>(mask);
    reduce_sums<<<dim3(NN / 256, BB), 256>>>();

    // join, then the output GEMM
    cudaStreamWaitEvent(0, evJoin, 0);
    out_gemm_bf<<<dim3(NN / 128, CC / 128, BB), 256>>>(x, mask, gamma, out);
}